// round 3
// baseline (speedup 1.0000x reference)
#include <cuda_runtime.h>
#include <cstdint>

#define N 8192
#define D 128
#define NUM_CLASSES 256
#define MARGIN 0.3f

#define BM 128
#define BN 128
#define BK 32
#define TM 8
#define TN 8

// Per-row accumulators (re-initialized every launch -> graph-replay safe).
__device__ float    g_sq[N];
__device__ int      g_cls[N];
__device__ float    g_pos_sum[N];
__device__ float    g_neg_sum[N];
__device__ unsigned g_pos_max[N];   // float bits; all dsq > 0 so uint order == float order
__device__ unsigned g_neg_min[N];

// ---------------------------------------------------------------------------
// Kernel 1: init. Detect target dtype (int64 vs int32-demoted), normalize
// classes, compute squared norms, reset accumulators.
// ---------------------------------------------------------------------------
__global__ void init_kernel(const float* __restrict__ x, const void* __restrict__ tgt,
                            int tgt_elems)
{
    __shared__ int s_is64;
    if (threadIdx.x == 0) {
        // If the buffer is int32 read as int64, the high word holds the next
        // target (0..255), making the value >= 2^32 unless it is 0.
        const long long* t64 = (const long long*)tgt;
        int is64 = 1;
        int probe = tgt_elems < 8 ? tgt_elems : 8;
        for (int i = 0; i < probe; i++) {
            long long v = t64[i];
            if (v < 0 || v >= NUM_CLASSES) { is64 = 0; break; }
        }
        s_is64 = is64;
    }
    __syncthreads();
    int r = blockIdx.x * blockDim.x + threadIdx.x;
    if (r < N) {
        int c;
        if (s_is64) c = (int)((const long long*)tgt)[r];
        else        c = ((const int*)tgt)[r];
        g_cls[r] = c;

        const float4* row = (const float4*)(x + (size_t)r * D);
        float s = 0.f;
        #pragma unroll
        for (int k = 0; k < D / 4; k++) {
            float4 v = row[k];
            s += v.x * v.x + v.y * v.y + v.z * v.z + v.w * v.w;
        }
        g_sq[r] = s;
        g_pos_sum[r] = 0.f;
        g_neg_sum[r] = 0.f;
        g_pos_max[r] = 0u;            // 0.0f (identity for max over dsq>0)
        g_neg_min[r] = 0x7F800000u;   // +inf
    }
}

// ---------------------------------------------------------------------------
// Kernel 2: fused X*X^T GEMM on the LOWER-TRIANGLE of tiles (by <= bx),
// 128x128 tile, 8x8 microtile, fp32. Each off-diagonal tile feeds BOTH the
// row-i reductions (row epilogue) and the row-j reductions (column epilogue,
// using symmetry dsq(i,j) == dsq(j,i)).
// ---------------------------------------------------------------------------
__global__ __launch_bounds__(256) void dist_kernel(const float* __restrict__ x)
{
    const int bx = blockIdx.x;
    const int by = blockIdx.y;
    if (bx < by) return;              // triangular: only by <= bx tiles do work

    __shared__ float As[BK][BM + 4];  // transposed: As[k][m]
    __shared__ float Bs[BK][BN + 4];
    __shared__ float    c_psum[BN];
    __shared__ float    c_nsum[BN];
    __shared__ unsigned c_pmax[BN];
    __shared__ unsigned c_nmin[BN];

    const int i0 = by * BM;
    const int j0 = bx * BN;
    const int tid = threadIdx.x;
    const int tx = tid & 15;          // column group
    const int ty = tid >> 4;          // row group
    const bool offdiag = (bx != by);

    float acc[TM][TN];
    #pragma unroll
    for (int a = 0; a < TM; a++)
        #pragma unroll
        for (int b = 0; b < TN; b++) acc[a][b] = 0.f;

    if (offdiag) {
        if (tid < BN) {
            c_psum[tid] = 0.f;
            c_nsum[tid] = 0.f;
            c_pmax[tid] = 0u;
            c_nmin[tid] = 0x7F800000u;
        }
    }

    for (int kb = 0; kb < D; kb += BK) {
        // fill tiles: 1024 float4 each, 4 per thread
        #pragma unroll
        for (int it = 0; it < 4; it++) {
            int f   = tid + it * 256;
            int row = f >> 3;
            int c4  = (f & 7) * 4;
            float4 va = *(const float4*)(x + (size_t)(i0 + row) * D + kb + c4);
            As[c4 + 0][row] = va.x;
            As[c4 + 1][row] = va.y;
            As[c4 + 2][row] = va.z;
            As[c4 + 3][row] = va.w;
            float4 vb = *(const float4*)(x + (size_t)(j0 + row) * D + kb + c4);
            Bs[c4 + 0][row] = vb.x;
            Bs[c4 + 1][row] = vb.y;
            Bs[c4 + 2][row] = vb.z;
            Bs[c4 + 3][row] = vb.w;
        }
        __syncthreads();

        #pragma unroll
        for (int k = 0; k < BK; k++) {
            float4 a0 = *(const float4*)&As[k][ty * 8];
            float4 a1 = *(const float4*)&As[k][ty * 8 + 4];
            float4 b0 = *(const float4*)&Bs[k][tx * 8];
            float4 b1 = *(const float4*)&Bs[k][tx * 8 + 4];
            float av[8] = {a0.x, a0.y, a0.z, a0.w, a1.x, a1.y, a1.z, a1.w};
            float bv[8] = {b0.x, b0.y, b0.z, b0.w, b1.x, b1.y, b1.z, b1.w};
            #pragma unroll
            for (int a = 0; a < TM; a++)
                #pragma unroll
                for (int b = 0; b < TN; b++)
                    acc[a][b] += av[a] * bv[b];
        }
        __syncthreads();
    }

    // ---- pass 0: convert dot products to dsq in-place ----
    float sqj[TN];
    int   clsj[TN];
    float sqi[TM];
    int   clsi[TM];
    #pragma unroll
    for (int b = 0; b < TN; b++) {
        int j = j0 + tx * 8 + b;
        sqj[b]  = g_sq[j];
        clsj[b] = g_cls[j];
    }
    #pragma unroll
    for (int a = 0; a < TM; a++) {
        int i = i0 + ty * 8 + a;
        sqi[a]  = g_sq[i];
        clsi[a] = g_cls[i];
    }
    #pragma unroll
    for (int a = 0; a < TM; a++)
        #pragma unroll
        for (int b = 0; b < TN; b++)
            acc[a][b] = fmaxf(sqi[a] + sqj[b] - 2.f * acc[a][b], 1e-12f);

    // ---- row epilogue: reductions over columns for rows i ----
    #pragma unroll
    for (int a = 0; a < TM; a++) {
        int   i = i0 + ty * 8 + a;
        float psum = 0.f, nsum = 0.f;
        float pmax = 0.f, nmin = __uint_as_float(0x7F800000u);
        #pragma unroll
        for (int b = 0; b < TN; b++) {
            int   j   = j0 + tx * 8 + b;
            float dsq = acc[a][b];
            if (clsi[a] == clsj[b]) {
                if (j != i) {                 // reference drops the self element
                    psum += dsq;
                    pmax  = fmaxf(pmax, dsq);
                }
            } else {
                nsum += dsq;
                nmin  = fminf(nmin, dsq);
            }
        }
        #pragma unroll
        for (int off = 8; off >= 1; off >>= 1) {
            psum += __shfl_xor_sync(0xffffffffu, psum, off, 16);
            nsum += __shfl_xor_sync(0xffffffffu, nsum, off, 16);
            pmax  = fmaxf(pmax, __shfl_xor_sync(0xffffffffu, pmax, off, 16));
            nmin  = fminf(nmin, __shfl_xor_sync(0xffffffffu, nmin, off, 16));
        }
        if (tx == 0) {
            atomicAdd(&g_pos_sum[i], psum);
            atomicAdd(&g_neg_sum[i], nsum);
            atomicMax(&g_pos_max[i], __float_as_uint(pmax));
            atomicMin(&g_neg_min[i], __float_as_uint(nmin));
        }
    }

    // ---- column epilogue (off-diagonal tiles only): by symmetry these are
    // the reductions for rows j over columns i. i != j always holds here. ----
    if (offdiag) {
        __syncthreads();   // c_* arrays initialized
        #pragma unroll
        for (int b = 0; b < TN; b++) {
            float psum = 0.f, nsum = 0.f;
            float pmax = 0.f, nmin = __uint_as_float(0x7F800000u);
            #pragma unroll
            for (int a = 0; a < TM; a++) {
                float dsq = acc[a][b];
                if (clsi[a] == clsj[b]) {
                    psum += dsq;
                    pmax  = fmaxf(pmax, dsq);
                } else {
                    nsum += dsq;
                    nmin  = fminf(nmin, dsq);
                }
            }
            int col = tx * 8 + b;
            atomicAdd(&c_psum[col], psum);
            atomicAdd(&c_nsum[col], nsum);
            atomicMax(&c_pmax[col], __float_as_uint(pmax));
            atomicMin(&c_nmin[col], __float_as_uint(nmin));
        }
        __syncthreads();
        if (tid < BN) {
            int j = j0 + tid;
            atomicAdd(&g_pos_sum[j], c_psum[tid]);
            atomicAdd(&g_neg_sum[j], c_nsum[tid]);
            atomicMax(&g_pos_max[j], c_pmax[tid]);
            atomicMin(&g_neg_min[j], c_nmin[tid]);
        }
    }
}

// ---------------------------------------------------------------------------
// Kernel 3: class histogram + per-row loss terms + mean.
// ---------------------------------------------------------------------------
__global__ void finalize_kernel(float* __restrict__ out)
{
    __shared__ int   hist[NUM_CLASSES];
    __shared__ float red[256];
    const int tid = threadIdx.x;

    if (tid < NUM_CLASSES) hist[tid] = 0;
    __syncthreads();
    for (int r = tid; r < N; r += 256) atomicAdd(&hist[g_cls[r]], 1);
    __syncthreads();

    float lsum = 0.f;
    for (int r = tid; r < N; r += 256) {
        int   h       = hist[g_cls[r]];
        float cnt_p   = (float)(h - 1);
        float cnt_n   = (float)(N - h);
        float sigma_p = g_pos_sum[r] / cnt_p;
        float sigma_n = g_neg_sum[r] / cnt_n;
        float ap = __uint_as_float(g_pos_max[r]) / sigma_p + 0.5f * logf(sigma_p);
        float an = __uint_as_float(g_neg_min[r]) / sigma_n + 0.5f * logf(sigma_n);
        lsum += fmaxf(ap - an + MARGIN, 0.f);
    }
    red[tid] = lsum;
    __syncthreads();
    for (int s = 128; s > 0; s >>= 1) {
        if (tid < s) red[tid] += red[tid + s];
        __syncthreads();
    }
    if (tid == 0) out[0] = red[0] / (float)N;
}

// ---------------------------------------------------------------------------
extern "C" void kernel_launch(void* const* d_in, const int* in_sizes, int n_in,
                              void* d_out, int out_size)
{
    const float* x = (const float*)d_in[0];
    const void*  t = d_in[1];
    int tgt_elems = (n_in > 1) ? in_sizes[1] : N;

    init_kernel<<<(N + 255) / 256, 256>>>(x, t, tgt_elems);
    dim3 grid(N / BN, N / BM);
    dist_kernel<<<grid, 256>>>(x);
    finalize_kernel<<<1, 256>>>((float*)d_out);
}

// round 4
// speedup vs baseline: 1.8503x; 1.8503x over previous
#include <cuda_runtime.h>
#include <cuda_bf16.h>
#include <cstdint>

#define N 8192
#define D 128
#define NUM_CLASSES 256
#define MARGIN 0.3f

#define BM 128
#define BN 128
#define BK 32
#define BKP 40   // padded smem row length (bf16 elems) = 80 bytes = 20 banks -> ldmatrix conflict-free

// Persistent device state (module globals; no allocation).
__device__ float         g_sq[N];
__device__ int           g_cls[N];
__device__ float         g_pos_sum[N];
__device__ float         g_neg_sum[N];
__device__ unsigned      g_pos_max[N];   // float bits; dsq > 0 so uint order == float order
__device__ unsigned      g_neg_min[N];
__device__ __nv_bfloat16 g_xhi[N * D];
__device__ __nv_bfloat16 g_xlo[N * D];

__device__ __forceinline__ unsigned su32(const void* p) {
    return (unsigned)__cvta_generic_to_shared(p);
}

#define LDMX4(r0, r1, r2, r3, addr)                                         \
    asm volatile("ldmatrix.sync.aligned.m8n8.x4.shared.b16 {%0,%1,%2,%3}, [%4];" \
                 : "=r"(r0), "=r"(r1), "=r"(r2), "=r"(r3) : "r"(addr))

#define MMA_BF16(c0, c1, c2, c3, a, b)                                      \
    asm volatile("mma.sync.aligned.m16n8k16.row.col.f32.bf16.bf16.f32 "     \
                 "{%0,%1,%2,%3}, {%4,%5,%6,%7}, {%8,%9}, {%0,%1,%2,%3};"    \
                 : "+f"(c0), "+f"(c1), "+f"(c2), "+f"(c3)                    \
                 : "r"((a)[0]), "r"((a)[1]), "r"((a)[2]), "r"((a)[3]),       \
                   "r"((b)[0]), "r"((b)[1]))

// ---------------------------------------------------------------------------
// Kernel 1: warp-per-row. Squared norms + bf16 hi/lo split of X.
// ---------------------------------------------------------------------------
__global__ void prep_kernel(const float* __restrict__ x)
{
    int gt   = blockIdx.x * blockDim.x + threadIdx.x;
    int row  = gt >> 5;
    int lane = gt & 31;
    if (row >= N) return;

    float4 v = ((const float4*)(x + (size_t)row * D))[lane];
    float s = v.x * v.x + v.y * v.y + v.z * v.z + v.w * v.w;
    #pragma unroll
    for (int o = 16; o; o >>= 1) s += __shfl_xor_sync(0xffffffffu, s, o);
    if (lane == 0) g_sq[row] = s;

    float f[4] = {v.x, v.y, v.z, v.w};
    unsigned short h[4], l[4];
    #pragma unroll
    for (int k = 0; k < 4; k++) {
        __nv_bfloat16 bh = __float2bfloat16(f[k]);
        __nv_bfloat16 bl = __float2bfloat16(f[k] - __bfloat162float(bh));
        h[k] = __bfloat16_as_ushort(bh);
        l[k] = __bfloat16_as_ushort(bl);
    }
    uint2 uh, ul;
    uh.x = (unsigned)h[0] | ((unsigned)h[1] << 16);
    uh.y = (unsigned)h[2] | ((unsigned)h[3] << 16);
    ul.x = (unsigned)l[0] | ((unsigned)l[1] << 16);
    ul.y = (unsigned)l[2] | ((unsigned)l[3] << 16);
    *(uint2*)(g_xhi + (size_t)row * D + lane * 4) = uh;
    *(uint2*)(g_xlo + (size_t)row * D + lane * 4) = ul;
}

// ---------------------------------------------------------------------------
// Kernel 2: targets (dtype auto-detect) + accumulator reset.
// ---------------------------------------------------------------------------
__global__ void init2_kernel(const void* __restrict__ tgt, int tgt_elems)
{
    __shared__ int s_is64;
    if (threadIdx.x == 0) {
        const long long* t64 = (const long long*)tgt;
        int is64 = 1;
        int probe = tgt_elems < 8 ? tgt_elems : 8;
        for (int i = 0; i < probe; i++) {
            long long v = t64[i];
            if (v < 0 || v >= NUM_CLASSES) { is64 = 0; break; }
        }
        s_is64 = is64;
    }
    __syncthreads();
    int r = blockIdx.x * blockDim.x + threadIdx.x;
    if (r < N) {
        int c;
        if (s_is64) c = (int)((const long long*)tgt)[r];
        else        c = ((const int*)tgt)[r];
        g_cls[r]     = c;
        g_pos_sum[r] = 0.f;
        g_neg_sum[r] = 0.f;
        g_pos_max[r] = 0u;
        g_neg_min[r] = 0x7F800000u;
    }
}

// ---------------------------------------------------------------------------
// Kernel 3: triangular tiled X*X^T via bf16 split mma.sync + fused epilogue.
// 8 warps per CTA in 2(M)x4(N); warp tile 64x32; dot = hi*hi + hi*lo + lo*hi.
// ---------------------------------------------------------------------------
__global__ __launch_bounds__(256) void dist_kernel()
{
    const int bx = blockIdx.x, by = blockIdx.y;
    if (bx < by) return;
    const bool offdiag = (bx != by);
    const int i0 = by * BM, j0 = bx * BN;

    __shared__ __nv_bfloat16 sAhi[BM * BKP], sAlo[BM * BKP];
    __shared__ __nv_bfloat16 sBhi[BN * BKP], sBlo[BN * BKP];
    __shared__ float    r_psum[BM], r_nsum[BM];
    __shared__ unsigned r_pmax[BM], r_nmin[BM];
    __shared__ float    c_psum[BN], c_nsum[BN];
    __shared__ unsigned c_pmax[BN], c_nmin[BN];

    const int tid = threadIdx.x;
    const int wid = tid >> 5, lane = tid & 31;
    const int warp_m = (wid >> 2) * 64;   // 0 or 64
    const int warp_n = (wid & 3) * 32;    // 0,32,64,96

    if (tid < BM) {
        r_psum[tid] = 0.f; r_nsum[tid] = 0.f; r_pmax[tid] = 0u; r_nmin[tid] = 0x7F800000u;
        c_psum[tid] = 0.f; c_nsum[tid] = 0.f; c_pmax[tid] = 0u; c_nmin[tid] = 0x7F800000u;
    }

    float C[8][8];
    #pragma unroll
    for (int a = 0; a < 8; a++)
        #pragma unroll
        for (int b = 0; b < 8; b++) C[a][b] = 0.f;

    // per-lane ldmatrix byte offsets within a 16x16 tile
    const unsigned aoff = (unsigned)(lane & 15) * (BKP * 2) + (unsigned)(lane >> 4) * 16;
    const unsigned boff = (unsigned)(((lane >> 4) & 1) * 8 + (lane & 7)) * (BKP * 2)
                        + (unsigned)((lane >> 3) & 1) * 16;

    const unsigned bAhi = su32(sAhi), bAlo = su32(sAlo);
    const unsigned bBhi = su32(sBhi), bBlo = su32(sBlo);

    for (int kb = 0; kb < D; kb += BK) {
        // fill 4 smem tiles: 128x32 bf16 each; 2 uint4 per thread per tile
        #pragma unroll
        for (int t = 0; t < 2; t++) {
            int idx = tid + t * 256;
            int row = idx >> 2, c8 = (idx & 3) * 8;
            size_t ga = (size_t)(i0 + row) * D + kb + c8;
            size_t gb = (size_t)(j0 + row) * D + kb + c8;
            *(uint4*)(sAhi + row * BKP + c8) = *(const uint4*)(g_xhi + ga);
            *(uint4*)(sAlo + row * BKP + c8) = *(const uint4*)(g_xlo + ga);
            *(uint4*)(sBhi + row * BKP + c8) = *(const uint4*)(g_xhi + gb);
            *(uint4*)(sBlo + row * BKP + c8) = *(const uint4*)(g_xlo + gb);
        }
        __syncthreads();

        #pragma unroll
        for (int ks = 0; ks < 2; ks++) {
            const unsigned kbyte = (unsigned)ks * 32;  // 16 bf16 = 32B
            unsigned Ahi[4][4], Alo[4][4], Bhi[4][2], Blo[4][2];
            #pragma unroll
            for (int mt = 0; mt < 4; mt++) {
                unsigned base = (unsigned)(warp_m + mt * 16) * (BKP * 2) + kbyte;
                LDMX4(Ahi[mt][0], Ahi[mt][1], Ahi[mt][2], Ahi[mt][3], bAhi + base + aoff);
                LDMX4(Alo[mt][0], Alo[mt][1], Alo[mt][2], Alo[mt][3], bAlo + base + aoff);
            }
            #pragma unroll
            for (int bq = 0; bq < 2; bq++) {
                unsigned base = (unsigned)(warp_n + bq * 16) * (BKP * 2) + kbyte;
                unsigned r0, r1, r2, r3;
                LDMX4(r0, r1, r2, r3, bBhi + base + boff);
                Bhi[2 * bq][0] = r0; Bhi[2 * bq][1] = r1;
                Bhi[2 * bq + 1][0] = r2; Bhi[2 * bq + 1][1] = r3;
                LDMX4(r0, r1, r2, r3, bBlo + base + boff);
                Blo[2 * bq][0] = r0; Blo[2 * bq][1] = r1;
                Blo[2 * bq + 1][0] = r2; Blo[2 * bq + 1][1] = r3;
            }
            #pragma unroll
            for (int mt = 0; mt < 4; mt++)
                #pragma unroll
                for (int nt = 0; nt < 4; nt++) {
                    MMA_BF16(C[2*mt][2*nt], C[2*mt][2*nt+1], C[2*mt+1][2*nt], C[2*mt+1][2*nt+1],
                             Ahi[mt], Bhi[nt]);
                    MMA_BF16(C[2*mt][2*nt], C[2*mt][2*nt+1], C[2*mt+1][2*nt], C[2*mt+1][2*nt+1],
                             Ahi[mt], Blo[nt]);
                    MMA_BF16(C[2*mt][2*nt], C[2*mt][2*nt+1], C[2*mt+1][2*nt], C[2*mt+1][2*nt+1],
                             Alo[mt], Bhi[nt]);
                }
        }
        __syncthreads();
    }

    // ---- epilogue ----
    const int rg = lane >> 2, cg = lane & 3;
    int   gi[8], gj[8], clsi[8], clsj[8];
    float sqi[8], sqj[8];
    #pragma unroll
    for (int mi = 0; mi < 8; mi++) {
        int lr = warp_m + (mi >> 1) * 16 + (mi & 1) * 8 + rg;
        gi[mi]   = i0 + lr;
        sqi[mi]  = g_sq[gi[mi]];
        clsi[mi] = g_cls[gi[mi]];
    }
    #pragma unroll
    for (int ci = 0; ci < 8; ci++) {
        int lc = warp_n + (ci >> 1) * 8 + 2 * cg + (ci & 1);
        gj[ci]   = j0 + lc;
        sqj[ci]  = g_sq[gj[ci]];
        clsj[ci] = g_cls[gj[ci]];
    }
    #pragma unroll
    for (int mi = 0; mi < 8; mi++)
        #pragma unroll
        for (int ci = 0; ci < 8; ci++)
            C[mi][ci] = fmaxf(sqi[mi] + sqj[ci] - 2.f * C[mi][ci], 1e-12f);

    // row pass: reductions over the 8 columns per thread, then quad shuffle
    #pragma unroll
    for (int mi = 0; mi < 8; mi++) {
        float psum = 0.f, nsum = 0.f;
        float pmax = 0.f, nmin = __uint_as_float(0x7F800000u);
        #pragma unroll
        for (int ci = 0; ci < 8; ci++) {
            float dsq = C[mi][ci];
            if (clsi[mi] == clsj[ci]) {
                if (gi[mi] != gj[ci]) {   // reference drops the self element
                    psum += dsq;
                    pmax  = fmaxf(pmax, dsq);
                }
            } else {
                nsum += dsq;
                nmin  = fminf(nmin, dsq);
            }
        }
        #pragma unroll
        for (int o = 1; o <= 2; o <<= 1) {
            psum += __shfl_xor_sync(0xffffffffu, psum, o);
            nsum += __shfl_xor_sync(0xffffffffu, nsum, o);
            pmax  = fmaxf(pmax, __shfl_xor_sync(0xffffffffu, pmax, o));
            nmin  = fminf(nmin, __shfl_xor_sync(0xffffffffu, nmin, o));
        }
        if (cg == 0) {
            int lr = gi[mi] - i0;
            atomicAdd(&r_psum[lr], psum);
            atomicAdd(&r_nsum[lr], nsum);
            atomicMax(&r_pmax[lr], __float_as_uint(pmax));
            atomicMin(&r_nmin[lr], __float_as_uint(nmin));
        }
    }

    // column pass (symmetry: these are row-j reductions) for off-diagonal tiles
    if (offdiag) {
        #pragma unroll
        for (int ci = 0; ci < 8; ci++) {
            float psum = 0.f, nsum = 0.f;
            float pmax = 0.f, nmin = __uint_as_float(0x7F800000u);
            #pragma unroll
            for (int mi = 0; mi < 8; mi++) {
                float dsq = C[mi][ci];
                if (clsi[mi] == clsj[ci]) {
                    psum += dsq;
                    pmax  = fmaxf(pmax, dsq);
                } else {
                    nsum += dsq;
                    nmin  = fminf(nmin, dsq);
                }
            }
            #pragma unroll
            for (int o = 4; o <= 16; o <<= 1) {
                psum += __shfl_xor_sync(0xffffffffu, psum, o);
                nsum += __shfl_xor_sync(0xffffffffu, nsum, o);
                pmax  = fmaxf(pmax, __shfl_xor_sync(0xffffffffu, pmax, o));
                nmin  = fminf(nmin, __shfl_xor_sync(0xffffffffu, nmin, o));
            }
            if (lane < 4) {
                int lc = gj[ci] - j0;
                atomicAdd(&c_psum[lc], psum);
                atomicAdd(&c_nsum[lc], nsum);
                atomicMax(&c_pmax[lc], __float_as_uint(pmax));
                atomicMin(&c_nmin[lc], __float_as_uint(nmin));
            }
        }
    }

    __syncthreads();
    if (tid < BM) {
        int i = i0 + tid;
        atomicAdd(&g_pos_sum[i], r_psum[tid]);
        atomicAdd(&g_neg_sum[i], r_nsum[tid]);
        atomicMax(&g_pos_max[i], r_pmax[tid]);
        atomicMin(&g_neg_min[i], r_nmin[tid]);
        if (offdiag) {
            int j = j0 + tid;
            atomicAdd(&g_pos_sum[j], c_psum[tid]);
            atomicAdd(&g_neg_sum[j], c_nsum[tid]);
            atomicMax(&g_pos_max[j], c_pmax[tid]);
            atomicMin(&g_neg_min[j], c_nmin[tid]);
        }
    }
}

// ---------------------------------------------------------------------------
// Kernel 4: class histogram + per-row loss terms + mean.
// ---------------------------------------------------------------------------
__global__ void finalize_kernel(float* __restrict__ out)
{
    __shared__ int   hist[NUM_CLASSES];
    __shared__ float red[256];
    const int tid = threadIdx.x;

    if (tid < NUM_CLASSES) hist[tid] = 0;
    __syncthreads();
    for (int r = tid; r < N; r += 256) atomicAdd(&hist[g_cls[r]], 1);
    __syncthreads();

    float lsum = 0.f;
    for (int r = tid; r < N; r += 256) {
        int   h       = hist[g_cls[r]];
        float cnt_p   = (float)(h - 1);
        float cnt_n   = (float)(N - h);
        float sigma_p = g_pos_sum[r] / cnt_p;
        float sigma_n = g_neg_sum[r] / cnt_n;
        float ap = __uint_as_float(g_pos_max[r]) / sigma_p + 0.5f * logf(sigma_p);
        float an = __uint_as_float(g_neg_min[r]) / sigma_n + 0.5f * logf(sigma_n);
        lsum += fmaxf(ap - an + MARGIN, 0.f);
    }
    red[tid] = lsum;
    __syncthreads();
    for (int s = 128; s > 0; s >>= 1) {
        if (tid < s) red[tid] += red[tid + s];
        __syncthreads();
    }
    if (tid == 0) out[0] = red[0] / (float)N;
}

// ---------------------------------------------------------------------------
extern "C" void kernel_launch(void* const* d_in, const int* in_sizes, int n_in,
                              void* d_out, int out_size)
{
    const float* x = (const float*)d_in[0];
    const void*  t = d_in[1];
    int tgt_elems = (n_in > 1) ? in_sizes[1] : N;

    prep_kernel<<<N / 8, 256>>>(x);          // 8 rows per 256-thread block
    init2_kernel<<<(N + 255) / 256, 256>>>(t, tgt_elems);
    dist_kernel<<<dim3(64, 64), 256>>>();
    finalize_kernel<<<1, 256>>>((float*)d_out);
}

// round 5
// speedup vs baseline: 2.3289x; 1.2587x over previous
#include <cuda_runtime.h>
#include <cuda_bf16.h>
#include <cstdint>

#define N 8192
#define D 128
#define NUM_CLASSES 256
#define MARGIN 0.3f

#define BM 128
#define BN 128
#define BK 32
#define BKP 40   // padded smem row length (bf16 elems) = 80 bytes = 20 banks -> ldmatrix conflict-free

// Persistent device state (module globals; no allocation).
__device__ float         g_sq[N];
__device__ int           g_cls[N];
__device__ float         g_pos_sum[N];
__device__ float         g_neg_sum[N];
__device__ unsigned      g_pos_max[N];   // float bits; dsq > 0 so uint order == float order
__device__ unsigned      g_neg_min[N];
__device__ int           g_hist[NUM_CLASSES];
__device__ __nv_bfloat16 g_xhi[N * D];
__device__ __nv_bfloat16 g_xlo[N * D];

__device__ __forceinline__ unsigned su32(const void* p) {
    return (unsigned)__cvta_generic_to_shared(p);
}

#define LDMX4(r0, r1, r2, r3, addr)                                         \
    asm volatile("ldmatrix.sync.aligned.m8n8.x4.shared.b16 {%0,%1,%2,%3}, [%4];" \
                 : "=r"(r0), "=r"(r1), "=r"(r2), "=r"(r3) : "r"(addr))

#define MMA_BF16(c0, c1, c2, c3, a, b)                                      \
    asm volatile("mma.sync.aligned.m16n8k16.row.col.f32.bf16.bf16.f32 "     \
                 "{%0,%1,%2,%3}, {%4,%5,%6,%7}, {%8,%9}, {%0,%1,%2,%3};"    \
                 : "+f"(c0), "+f"(c1), "+f"(c2), "+f"(c3)                    \
                 : "r"((a)[0]), "r"((a)[1]), "r"((a)[2]), "r"((a)[3]),       \
                   "r"((b)[0]), "r"((b)[1]))

// ---------------------------------------------------------------------------
// Kernel 1: warp-per-row. Squared norms + bf16 hi/lo split of X.
// ---------------------------------------------------------------------------
__global__ void prep_kernel(const float* __restrict__ x)
{
    int gt   = blockIdx.x * blockDim.x + threadIdx.x;
    int row  = gt >> 5;
    int lane = gt & 31;
    if (row >= N) return;

    float4 v = ((const float4*)(x + (size_t)row * D))[lane];
    float s = v.x * v.x + v.y * v.y + v.z * v.z + v.w * v.w;
    #pragma unroll
    for (int o = 16; o; o >>= 1) s += __shfl_xor_sync(0xffffffffu, s, o);
    if (lane == 0) g_sq[row] = s;

    float f[4] = {v.x, v.y, v.z, v.w};
    unsigned short h[4], l[4];
    #pragma unroll
    for (int k = 0; k < 4; k++) {
        __nv_bfloat16 bh = __float2bfloat16(f[k]);
        __nv_bfloat16 bl = __float2bfloat16(f[k] - __bfloat162float(bh));
        h[k] = __bfloat16_as_ushort(bh);
        l[k] = __bfloat16_as_ushort(bl);
    }
    uint2 uh, ul;
    uh.x = (unsigned)h[0] | ((unsigned)h[1] << 16);
    uh.y = (unsigned)h[2] | ((unsigned)h[3] << 16);
    ul.x = (unsigned)l[0] | ((unsigned)l[1] << 16);
    ul.y = (unsigned)l[2] | ((unsigned)l[3] << 16);
    *(uint2*)(g_xhi + (size_t)row * D + lane * 4) = uh;
    *(uint2*)(g_xlo + (size_t)row * D + lane * 4) = ul;
}

// ---------------------------------------------------------------------------
// Kernel 2: targets (dtype auto-detect) + accumulator/hist/out reset.
// ---------------------------------------------------------------------------
__global__ void init2_kernel(const void* __restrict__ tgt, int tgt_elems,
                             float* __restrict__ out)
{
    __shared__ int s_is64;
    if (threadIdx.x == 0) {
        const long long* t64 = (const long long*)tgt;
        int is64 = 1;
        int probe = tgt_elems < 8 ? tgt_elems : 8;
        for (int i = 0; i < probe; i++) {
            long long v = t64[i];
            if (v < 0 || v >= NUM_CLASSES) { is64 = 0; break; }
        }
        s_is64 = is64;
    }
    __syncthreads();
    int r = blockIdx.x * blockDim.x + threadIdx.x;
    if (r < N) {
        int c;
        if (s_is64) c = (int)((const long long*)tgt)[r];
        else        c = ((const int*)tgt)[r];
        g_cls[r]     = c;
        g_pos_sum[r] = 0.f;
        g_neg_sum[r] = 0.f;
        g_pos_max[r] = 0u;
        g_neg_min[r] = 0x7F800000u;
    }
    if (r < NUM_CLASSES) g_hist[r] = 0;
    if (r == 0) out[0] = 0.f;
}

// ---------------------------------------------------------------------------
// Kernel 2b: class histogram (global atomics; runs after init2).
// ---------------------------------------------------------------------------
__global__ void hist_kernel()
{
    int r = blockIdx.x * blockDim.x + threadIdx.x;
    if (r < N) atomicAdd(&g_hist[g_cls[r]], 1);
}

// ---------------------------------------------------------------------------
// Kernel 3: triangular tiled X*X^T via bf16 split mma.sync + fused epilogue.
// 8 warps per CTA in 2(M)x4(N); warp tile 64x32; dot = hi*hi + hi*lo + lo*hi.
// ---------------------------------------------------------------------------
__global__ __launch_bounds__(256) void dist_kernel()
{
    const int bx = blockIdx.x, by = blockIdx.y;
    if (bx < by) return;
    const bool offdiag = (bx != by);
    const int i0 = by * BM, j0 = bx * BN;

    __shared__ __nv_bfloat16 sAhi[BM * BKP], sAlo[BM * BKP];
    __shared__ __nv_bfloat16 sBhi[BN * BKP], sBlo[BN * BKP];
    __shared__ float    r_psum[BM], r_nsum[BM];
    __shared__ unsigned r_pmax[BM], r_nmin[BM];
    __shared__ float    c_psum[BN], c_nsum[BN];
    __shared__ unsigned c_pmax[BN], c_nmin[BN];

    const int tid = threadIdx.x;
    const int wid = tid >> 5, lane = tid & 31;
    const int warp_m = (wid >> 2) * 64;   // 0 or 64
    const int warp_n = (wid & 3) * 32;    // 0,32,64,96

    if (tid < BM) {
        r_psum[tid] = 0.f; r_nsum[tid] = 0.f; r_pmax[tid] = 0u; r_nmin[tid] = 0x7F800000u;
        c_psum[tid] = 0.f; c_nsum[tid] = 0.f; c_pmax[tid] = 0u; c_nmin[tid] = 0x7F800000u;
    }

    float C[8][8];
    #pragma unroll
    for (int a = 0; a < 8; a++)
        #pragma unroll
        for (int b = 0; b < 8; b++) C[a][b] = 0.f;

    // per-lane ldmatrix byte offsets within a 16x16 tile
    const unsigned aoff = (unsigned)(lane & 15) * (BKP * 2) + (unsigned)(lane >> 4) * 16;
    const unsigned boff = (unsigned)(((lane >> 4) & 1) * 8 + (lane & 7)) * (BKP * 2)
                        + (unsigned)((lane >> 3) & 1) * 16;

    const unsigned bAhi = su32(sAhi), bAlo = su32(sAlo);
    const unsigned bBhi = su32(sBhi), bBlo = su32(sBlo);

    for (int kb = 0; kb < D; kb += BK) {
        // fill 4 smem tiles: 128x32 bf16 each; 2 uint4 per thread per tile
        #pragma unroll
        for (int t = 0; t < 2; t++) {
            int idx = tid + t * 256;
            int row = idx >> 2, c8 = (idx & 3) * 8;
            size_t ga = (size_t)(i0 + row) * D + kb + c8;
            size_t gb = (size_t)(j0 + row) * D + kb + c8;
            *(uint4*)(sAhi + row * BKP + c8) = *(const uint4*)(g_xhi + ga);
            *(uint4*)(sAlo + row * BKP + c8) = *(const uint4*)(g_xlo + ga);
            *(uint4*)(sBhi + row * BKP + c8) = *(const uint4*)(g_xhi + gb);
            *(uint4*)(sBlo + row * BKP + c8) = *(const uint4*)(g_xlo + gb);
        }
        __syncthreads();

        #pragma unroll
        for (int ks = 0; ks < 2; ks++) {
            const unsigned kbyte = (unsigned)ks * 32;  // 16 bf16 = 32B
            unsigned Ahi[4][4], Alo[4][4], Bhi[4][2], Blo[4][2];
            #pragma unroll
            for (int mt = 0; mt < 4; mt++) {
                unsigned base = (unsigned)(warp_m + mt * 16) * (BKP * 2) + kbyte;
                LDMX4(Ahi[mt][0], Ahi[mt][1], Ahi[mt][2], Ahi[mt][3], bAhi + base + aoff);
                LDMX4(Alo[mt][0], Alo[mt][1], Alo[mt][2], Alo[mt][3], bAlo + base + aoff);
            }
            #pragma unroll
            for (int bq = 0; bq < 2; bq++) {
                unsigned base = (unsigned)(warp_n + bq * 16) * (BKP * 2) + kbyte;
                unsigned r0, r1, r2, r3;
                LDMX4(r0, r1, r2, r3, bBhi + base + boff);
                Bhi[2 * bq][0] = r0; Bhi[2 * bq][1] = r1;
                Bhi[2 * bq + 1][0] = r2; Bhi[2 * bq + 1][1] = r3;
                LDMX4(r0, r1, r2, r3, bBlo + base + boff);
                Blo[2 * bq][0] = r0; Blo[2 * bq][1] = r1;
                Blo[2 * bq + 1][0] = r2; Blo[2 * bq + 1][1] = r3;
            }
            #pragma unroll
            for (int mt = 0; mt < 4; mt++)
                #pragma unroll
                for (int nt = 0; nt < 4; nt++) {
                    MMA_BF16(C[2*mt][2*nt], C[2*mt][2*nt+1], C[2*mt+1][2*nt], C[2*mt+1][2*nt+1],
                             Ahi[mt], Bhi[nt]);
                    MMA_BF16(C[2*mt][2*nt], C[2*mt][2*nt+1], C[2*mt+1][2*nt], C[2*mt+1][2*nt+1],
                             Ahi[mt], Blo[nt]);
                    MMA_BF16(C[2*mt][2*nt], C[2*mt][2*nt+1], C[2*mt+1][2*nt], C[2*mt+1][2*nt+1],
                             Alo[mt], Bhi[nt]);
                }
        }
        __syncthreads();
    }

    // ---- epilogue ----
    const int rg = lane >> 2, cg = lane & 3;
    int   gi[8], gj[8], clsi[8], clsj[8];
    float sqi[8], sqj[8];
    #pragma unroll
    for (int mi = 0; mi < 8; mi++) {
        int lr = warp_m + (mi >> 1) * 16 + (mi & 1) * 8 + rg;
        gi[mi]   = i0 + lr;
        sqi[mi]  = g_sq[gi[mi]];
        clsi[mi] = g_cls[gi[mi]];
    }
    #pragma unroll
    for (int ci = 0; ci < 8; ci++) {
        int lc = warp_n + (ci >> 1) * 8 + 2 * cg + (ci & 1);
        gj[ci]   = j0 + lc;
        sqj[ci]  = g_sq[gj[ci]];
        clsj[ci] = g_cls[gj[ci]];
    }
    #pragma unroll
    for (int mi = 0; mi < 8; mi++)
        #pragma unroll
        for (int ci = 0; ci < 8; ci++)
            C[mi][ci] = fmaxf(sqi[mi] + sqj[ci] - 2.f * C[mi][ci], 1e-12f);

    // row pass: reductions over the 8 columns per thread, then quad shuffle
    #pragma unroll
    for (int mi = 0; mi < 8; mi++) {
        float psum = 0.f, nsum = 0.f;
        float pmax = 0.f, nmin = __uint_as_float(0x7F800000u);
        #pragma unroll
        for (int ci = 0; ci < 8; ci++) {
            float dsq = C[mi][ci];
            if (clsi[mi] == clsj[ci]) {
                if (gi[mi] != gj[ci]) {   // reference drops the self element
                    psum += dsq;
                    pmax  = fmaxf(pmax, dsq);
                }
            } else {
                nsum += dsq;
                nmin  = fminf(nmin, dsq);
            }
        }
        #pragma unroll
        for (int o = 1; o <= 2; o <<= 1) {
            psum += __shfl_xor_sync(0xffffffffu, psum, o);
            nsum += __shfl_xor_sync(0xffffffffu, nsum, o);
            pmax  = fmaxf(pmax, __shfl_xor_sync(0xffffffffu, pmax, o));
            nmin  = fminf(nmin, __shfl_xor_sync(0xffffffffu, nmin, o));
        }
        if (cg == 0) {
            int lr = gi[mi] - i0;
            atomicAdd(&r_psum[lr], psum);
            atomicAdd(&r_nsum[lr], nsum);
            atomicMax(&r_pmax[lr], __float_as_uint(pmax));
            atomicMin(&r_nmin[lr], __float_as_uint(nmin));
        }
    }

    // column pass (symmetry: these are row-j reductions) for off-diagonal tiles
    if (offdiag) {
        #pragma unroll
        for (int ci = 0; ci < 8; ci++) {
            float psum = 0.f, nsum = 0.f;
            float pmax = 0.f, nmin = __uint_as_float(0x7F800000u);
            #pragma unroll
            for (int mi = 0; mi < 8; mi++) {
                float dsq = C[mi][ci];
                if (clsi[mi] == clsj[ci]) {
                    psum += dsq;
                    pmax  = fmaxf(pmax, dsq);
                } else {
                    nsum += dsq;
                    nmin  = fminf(nmin, dsq);
                }
            }
            #pragma unroll
            for (int o = 4; o <= 16; o <<= 1) {
                psum += __shfl_xor_sync(0xffffffffu, psum, o);
                nsum += __shfl_xor_sync(0xffffffffu, nsum, o);
                pmax  = fmaxf(pmax, __shfl_xor_sync(0xffffffffu, pmax, o));
                nmin  = fminf(nmin, __shfl_xor_sync(0xffffffffu, nmin, o));
            }
            if (lane < 4) {
                int lc = gj[ci] - j0;
                atomicAdd(&c_psum[lc], psum);
                atomicAdd(&c_nsum[lc], nsum);
                atomicMax(&c_pmax[lc], __float_as_uint(pmax));
                atomicMin(&c_nmin[lc], __float_as_uint(nmin));
            }
        }
    }

    __syncthreads();
    if (tid < BM) {
        int i = i0 + tid;
        atomicAdd(&g_pos_sum[i], r_psum[tid]);
        atomicAdd(&g_neg_sum[i], r_nsum[tid]);
        atomicMax(&g_pos_max[i], r_pmax[tid]);
        atomicMin(&g_neg_min[i], r_nmin[tid]);
        if (offdiag) {
            int j = j0 + tid;
            atomicAdd(&g_pos_sum[j], c_psum[tid]);
            atomicAdd(&g_neg_sum[j], c_nsum[tid]);
            atomicMax(&g_pos_max[j], c_pmax[tid]);
            atomicMin(&g_neg_min[j], c_nmin[tid]);
        }
    }
}

// ---------------------------------------------------------------------------
// Kernel 4: per-row loss terms + mean. 32 blocks; one atomicAdd per block.
// ---------------------------------------------------------------------------
__global__ void finalize_kernel(float* __restrict__ out)
{
    __shared__ float red[256];
    const int tid = threadIdx.x;
    const int r   = blockIdx.x * 256 + tid;

    int   h       = g_hist[g_cls[r]];
    float cnt_p   = (float)(h - 1);
    float cnt_n   = (float)(N - h);
    float sigma_p = g_pos_sum[r] / cnt_p;
    float sigma_n = g_neg_sum[r] / cnt_n;
    float ap = __uint_as_float(g_pos_max[r]) / sigma_p + 0.5f * logf(sigma_p);
    float an = __uint_as_float(g_neg_min[r]) / sigma_n + 0.5f * logf(sigma_n);
    float lsum = fmaxf(ap - an + MARGIN, 0.f);

    red[tid] = lsum;
    __syncthreads();
    #pragma unroll
    for (int s = 128; s > 0; s >>= 1) {
        if (tid < s) red[tid] += red[tid + s];
        __syncthreads();
    }
    if (tid == 0) atomicAdd(out, red[0] * (1.f / (float)N));
}

// ---------------------------------------------------------------------------
extern "C" void kernel_launch(void* const* d_in, const int* in_sizes, int n_in,
                              void* d_out, int out_size)
{
    const float* x = (const float*)d_in[0];
    const void*  t = d_in[1];
    int tgt_elems = (n_in > 1) ? in_sizes[1] : N;

    prep_kernel<<<N / 8, 256>>>(x);          // 8 rows per 256-thread block
    init2_kernel<<<(N + 255) / 256, 256>>>(t, tgt_elems, (float*)d_out);
    hist_kernel<<<(N + 255) / 256, 256>>>();
    dist_kernel<<<dim3(64, 64), 256>>>();
    finalize_kernel<<<N / 256, 256>>>((float*)d_out);
}

// round 7
// speedup vs baseline: 2.7890x; 1.1976x over previous
#include <cuda_runtime.h>
#include <cuda_bf16.h>
#include <cstdint>

#define N 8192
#define D 128
#define NUM_CLASSES 256
#define MARGIN 0.3f

#define BM 128
#define BN 128
#define BKP 40                        // padded row: 80B = 20 banks, ldmatrix conflict-free
#define CHUNK_ELEMS (128 * BKP)       // 5120 bf16 per (rowblock, kchunk)
#define CHUNK_BYTES (CHUNK_ELEMS * 2) // 10240 B
#define STAGE_BYTES (4 * CHUNK_BYTES) // Ahi,Alo,Bhi,Blo = 40960 B
#define SMEM_DATA   (2 * STAGE_BYTES) // double buffered = 81920 B
#define SMEM_TOTAL  (SMEM_DATA + 16)  // + 2 mbarriers

// Persistent device state (module globals; no allocation).
__device__ float    g_sq[N];
__device__ int      g_cls[N];
__device__ float    g_pos_sum[N];
__device__ float    g_neg_sum[N];
__device__ unsigned g_pos_max[N];     // float bits; dsq > 0 so uint order == float order
__device__ unsigned g_neg_min[N];
__device__ int      g_hist[NUM_CLASSES];
// tile-major, pre-padded: [block 0..63][kchunk 0..3][row 0..127 * BKP + col]
__device__ __align__(16) __nv_bfloat16 g_xhi[N * 4 * BKP];
__device__ __align__(16) __nv_bfloat16 g_xlo[N * 4 * BKP];

__device__ __forceinline__ unsigned su32(const void* p) {
    return (unsigned)__cvta_generic_to_shared(p);
}

#define LDMX4(r0, r1, r2, r3, addr)                                         \
    asm volatile("ldmatrix.sync.aligned.m8n8.x4.shared.b16 {%0,%1,%2,%3}, [%4];" \
                 : "=r"(r0), "=r"(r1), "=r"(r2), "=r"(r3) : "r"(addr))

#define MMA_BF16(c0, c1, c2, c3, a, b)                                      \
    asm volatile("mma.sync.aligned.m16n8k16.row.col.f32.bf16.bf16.f32 "     \
                 "{%0,%1,%2,%3}, {%4,%5,%6,%7}, {%8,%9}, {%0,%1,%2,%3};"    \
                 : "+f"(c0), "+f"(c1), "+f"(c2), "+f"(c3)                    \
                 : "r"((a)[0]), "r"((a)[1]), "r"((a)[2]), "r"((a)[3]),       \
                   "r"((b)[0]), "r"((b)[1]))

__device__ __forceinline__ void mbar_wait(unsigned mbar, unsigned parity) {
    asm volatile("{\n\t.reg .pred P;\n\t"
                 "WL%=:\n\t"
                 "mbarrier.try_wait.parity.acquire.cta.shared::cta.b64 P, [%0], %1, 0x989680;\n\t"
                 "@P bra WD%=;\n\t"
                 "bra WL%=;\n\t"
                 "WD%=:\n\t}"
                 :: "r"(mbar), "r"(parity) : "memory");
}

// ---------------------------------------------------------------------------
// Kernel 1: warp-per-row. Squared norms + bf16 hi/lo split written in the
// padded tile-major layout so dist_kernel can bulk-copy chunks verbatim.
// ---------------------------------------------------------------------------
__global__ void prep_kernel(const float* __restrict__ x)
{
    int gt   = blockIdx.x * blockDim.x + threadIdx.x;
    int row  = gt >> 5;
    int lane = gt & 31;
    if (row >= N) return;

    float4 v = ((const float4*)(x + (size_t)row * D))[lane];
    float s = v.x * v.x + v.y * v.y + v.z * v.z + v.w * v.w;
    #pragma unroll
    for (int o = 16; o; o >>= 1) s += __shfl_xor_sync(0xffffffffu, s, o);
    if (lane == 0) g_sq[row] = s;

    float f[4] = {v.x, v.y, v.z, v.w};
    unsigned short h[4], l[4];
    #pragma unroll
    for (int k = 0; k < 4; k++) {
        __nv_bfloat16 bh = __float2bfloat16(f[k]);
        __nv_bfloat16 bl = __float2bfloat16(f[k] - __bfloat162float(bh));
        h[k] = __bfloat16_as_ushort(bh);
        l[k] = __bfloat16_as_ushort(bl);
    }
    uint2 uh, ul;
    uh.x = (unsigned)h[0] | ((unsigned)h[1] << 16);
    uh.y = (unsigned)h[2] | ((unsigned)h[3] << 16);
    ul.x = (unsigned)l[0] | ((unsigned)l[1] << 16);
    ul.y = (unsigned)l[2] | ((unsigned)l[3] << 16);

    // lane covers global cols 4*lane .. 4*lane+3  ->  kchunk = lane>>3, c = (lane&7)*4
    int blk = row >> 7, r = row & 127;
    size_t off = (size_t)(blk * 4 + (lane >> 3)) * CHUNK_ELEMS + r * BKP + (lane & 7) * 4;
    *(uint2*)(g_xhi + off) = uh;
    *(uint2*)(g_xlo + off) = ul;
}

// ---------------------------------------------------------------------------
// Kernel 2: targets (dtype auto-detect) + accumulator/hist/out reset.
// ---------------------------------------------------------------------------
__global__ void init2_kernel(const void* __restrict__ tgt, int tgt_elems,
                             float* __restrict__ out)
{
    __shared__ int s_is64;
    if (threadIdx.x == 0) {
        const long long* t64 = (const long long*)tgt;
        int is64 = 1;
        int probe = tgt_elems < 8 ? tgt_elems : 8;
        for (int i = 0; i < probe; i++) {
            long long v = t64[i];
            if (v < 0 || v >= NUM_CLASSES) { is64 = 0; break; }
        }
        s_is64 = is64;
    }
    __syncthreads();
    int r = blockIdx.x * blockDim.x + threadIdx.x;
    if (r < N) {
        int c;
        if (s_is64) c = (int)((const long long*)tgt)[r];
        else        c = ((const int*)tgt)[r];
        g_cls[r]     = c;
        g_pos_sum[r] = 0.f;
        g_neg_sum[r] = 0.f;
        g_pos_max[r] = 0u;
        g_neg_min[r] = 0x7F800000u;
    }
    if (r < NUM_CLASSES) g_hist[r] = 0;
    if (r == 0) out[0] = 0.f;
}

__global__ void hist_kernel()
{
    int r = blockIdx.x * blockDim.x + threadIdx.x;
    if (r < N) atomicAdd(&g_hist[g_cls[r]], 1);
}

// ---------------------------------------------------------------------------
// Kernel 3: triangular tiled X*X^T, bf16-split mma.sync, cp.async.bulk
// double-buffered tile feed (no LDG/STS through L1tex for tile data).
// ---------------------------------------------------------------------------
__device__ __forceinline__ void issue_stage(unsigned sbase, int s, int kb,
                                            int by, int bx)
{
    unsigned mbar = sbase + SMEM_DATA + s * 8;
    asm volatile("mbarrier.arrive.expect_tx.shared.b64 _, [%0], %1;"
                 :: "r"(mbar), "r"((unsigned)STAGE_BYTES) : "memory");
    const __nv_bfloat16* srcs[4] = {
        g_xhi + (size_t)(by * 4 + kb) * CHUNK_ELEMS,
        g_xlo + (size_t)(by * 4 + kb) * CHUNK_ELEMS,
        g_xhi + (size_t)(bx * 4 + kb) * CHUNK_ELEMS,
        g_xlo + (size_t)(bx * 4 + kb) * CHUNK_ELEMS
    };
    #pragma unroll
    for (int o = 0; o < 4; o++) {
        unsigned dst = sbase + (unsigned)(s * 4 + o) * CHUNK_BYTES;
        asm volatile("cp.async.bulk.shared::cluster.global.mbarrier::complete_tx::bytes "
                     "[%0], [%1], %2, [%3];"
                     :: "r"(dst), "l"(srcs[o]), "r"((unsigned)CHUNK_BYTES), "r"(mbar)
                     : "memory");
    }
}

__global__ __launch_bounds__(256) void dist_kernel()
{
    const int bx = blockIdx.x, by = blockIdx.y;
    if (bx < by) return;
    const bool offdiag = (bx != by);
    const int i0 = by * BM, j0 = bx * BN;

    extern __shared__ char smem[];
    const unsigned sbase = su32(smem);

    __shared__ float    r_psum[BM], r_nsum[BM];
    __shared__ unsigned r_pmax[BM], r_nmin[BM];
    __shared__ float    c_psum[BN], c_nsum[BN];
    __shared__ unsigned c_pmax[BN], c_nmin[BN];

    const int tid = threadIdx.x;
    const int wid = tid >> 5, lane = tid & 31;
    const int warp_m = (wid >> 2) * 64;   // 0 or 64
    const int warp_n = (wid & 3) * 32;    // 0,32,64,96

    if (tid < BM) {
        r_psum[tid] = 0.f; r_nsum[tid] = 0.f; r_pmax[tid] = 0u; r_nmin[tid] = 0x7F800000u;
        c_psum[tid] = 0.f; c_nsum[tid] = 0.f; c_pmax[tid] = 0u; c_nmin[tid] = 0x7F800000u;
    }
    if (tid == 0) {
        asm volatile("mbarrier.init.shared.b64 [%0], %1;"
                     :: "r"(sbase + SMEM_DATA), "r"(1u) : "memory");
        asm volatile("mbarrier.init.shared.b64 [%0], %1;"
                     :: "r"(sbase + SMEM_DATA + 8), "r"(1u) : "memory");
    }
    __syncthreads();
    if (tid == 0) {
        issue_stage(sbase, 0, 0, by, bx);
        issue_stage(sbase, 1, 1, by, bx);
    }

    float C[8][8];
    #pragma unroll
    for (int a = 0; a < 8; a++)
        #pragma unroll
        for (int b = 0; b < 8; b++) C[a][b] = 0.f;

    // per-lane ldmatrix byte offsets within a 16x16 tile (80B row pitch)
    const unsigned aoff = (unsigned)(lane & 15) * (BKP * 2) + (unsigned)(lane >> 4) * 16;
    const unsigned boff = (unsigned)(((lane >> 4) & 1) * 8 + (lane & 7)) * (BKP * 2)
                        + (unsigned)((lane >> 3) & 1) * 16;

    for (int kb = 0; kb < 4; kb++) {
        const int s = kb & 1;
        mbar_wait(sbase + SMEM_DATA + s * 8, (unsigned)(kb >> 1));

        const unsigned sb   = sbase + (unsigned)s * STAGE_BYTES;
        const unsigned bAhi = sb;
        const unsigned bAlo = sb + CHUNK_BYTES;
        const unsigned bBhi = sb + 2 * CHUNK_BYTES;
        const unsigned bBlo = sb + 3 * CHUNK_BYTES;

        #pragma unroll
        for (int ks = 0; ks < 2; ks++) {
            const unsigned kbyte = (unsigned)ks * 32;  // 16 bf16 = 32B
            unsigned Ahi[4][4], Alo[4][4], Bhi[4][2], Blo[4][2];
            #pragma unroll
            for (int mt = 0; mt < 4; mt++) {
                unsigned base = (unsigned)(warp_m + mt * 16) * (BKP * 2) + kbyte;
                LDMX4(Ahi[mt][0], Ahi[mt][1], Ahi[mt][2], Ahi[mt][3], bAhi + base + aoff);
                LDMX4(Alo[mt][0], Alo[mt][1], Alo[mt][2], Alo[mt][3], bAlo + base + aoff);
            }
            #pragma unroll
            for (int bq = 0; bq < 2; bq++) {
                unsigned base = (unsigned)(warp_n + bq * 16) * (BKP * 2) + kbyte;
                unsigned r0, r1, r2, r3;
                LDMX4(r0, r1, r2, r3, bBhi + base + boff);
                Bhi[2 * bq][0] = r0; Bhi[2 * bq][1] = r1;
                Bhi[2 * bq + 1][0] = r2; Bhi[2 * bq + 1][1] = r3;
                LDMX4(r0, r1, r2, r3, bBlo + base + boff);
                Blo[2 * bq][0] = r0; Blo[2 * bq][1] = r1;
                Blo[2 * bq + 1][0] = r2; Blo[2 * bq + 1][1] = r3;
            }
            #pragma unroll
            for (int mt = 0; mt < 4; mt++)
                #pragma unroll
                for (int nt = 0; nt < 4; nt++) {
                    MMA_BF16(C[2*mt][2*nt], C[2*mt][2*nt+1], C[2*mt+1][2*nt], C[2*mt+1][2*nt+1],
                             Ahi[mt], Bhi[nt]);
                    MMA_BF16(C[2*mt][2*nt], C[2*mt][2*nt+1], C[2*mt+1][2*nt], C[2*mt+1][2*nt+1],
                             Ahi[mt], Blo[nt]);
                    MMA_BF16(C[2*mt][2*nt], C[2*mt][2*nt+1], C[2*mt+1][2*nt], C[2*mt+1][2*nt+1],
                             Alo[mt], Bhi[nt]);
                }
        }
        __syncthreads();                 // all warps done reading stage s
        if (tid == 0 && kb < 2) issue_stage(sbase, s, kb + 2, by, bx);
    }

    // ---- epilogue ----
    const int rg = lane >> 2, cg = lane & 3;
    int   gi[8], gj[8], clsi[8], clsj[8];
    float sqi[8], sqj[8];
    #pragma unroll
    for (int mi = 0; mi < 8; mi++) {
        int lr = warp_m + (mi >> 1) * 16 + (mi & 1) * 8 + rg;
        gi[mi]   = i0 + lr;
        sqi[mi]  = g_sq[gi[mi]];
        clsi[mi] = g_cls[gi[mi]];
    }
    #pragma unroll
    for (int ci = 0; ci < 8; ci++) {
        int lc = warp_n + (ci >> 1) * 8 + 2 * cg + (ci & 1);
        gj[ci]   = j0 + lc;
        sqj[ci]  = g_sq[gj[ci]];
        clsj[ci] = g_cls[gj[ci]];
    }
    #pragma unroll
    for (int mi = 0; mi < 8; mi++)
        #pragma unroll
        for (int ci = 0; ci < 8; ci++)
            C[mi][ci] = fmaxf(sqi[mi] + sqj[ci] - 2.f * C[mi][ci], 1e-12f);

    // row pass: reductions over the 8 columns per thread, then quad shuffle
    #pragma unroll
    for (int mi = 0; mi < 8; mi++) {
        float psum = 0.f, nsum = 0.f;
        float pmax = 0.f, nmin = __uint_as_float(0x7F800000u);
        #pragma unroll
        for (int ci = 0; ci < 8; ci++) {
            float dsq = C[mi][ci];
            if (clsi[mi] == clsj[ci]) {
                if (gi[mi] != gj[ci]) {   // reference drops the self element
                    psum += dsq;
                    pmax  = fmaxf(pmax, dsq);
                }
            } else {
                nsum += dsq;
                nmin  = fminf(nmin, dsq);
            }
        }
        #pragma unroll
        for (int o = 1; o <= 2; o <<= 1) {
            psum += __shfl_xor_sync(0xffffffffu, psum, o);
            nsum += __shfl_xor_sync(0xffffffffu, nsum, o);
            pmax  = fmaxf(pmax, __shfl_xor_sync(0xffffffffu, pmax, o));
            nmin  = fminf(nmin, __shfl_xor_sync(0xffffffffu, nmin, o));
        }
        if (cg == 0) {
            int lr = gi[mi] - i0;
            atomicAdd(&r_psum[lr], psum);
            atomicAdd(&r_nsum[lr], nsum);
            atomicMax(&r_pmax[lr], __float_as_uint(pmax));
            atomicMin(&r_nmin[lr], __float_as_uint(nmin));
        }
    }

    // column pass (symmetry: row-j reductions) for off-diagonal tiles
    if (offdiag) {
        #pragma unroll
        for (int ci = 0; ci < 8; ci++) {
            float psum = 0.f, nsum = 0.f;
            float pmax = 0.f, nmin = __uint_as_float(0x7F800000u);
            #pragma unroll
            for (int mi = 0; mi < 8; mi++) {
                float dsq = C[mi][ci];
                if (clsi[mi] == clsj[ci]) {
                    psum += dsq;
                    pmax  = fmaxf(pmax, dsq);
                } else {
                    nsum += dsq;
                    nmin  = fminf(nmin, dsq);
                }
            }
            #pragma unroll
            for (int o = 4; o <= 16; o <<= 1) {
                psum += __shfl_xor_sync(0xffffffffu, psum, o);
                nsum += __shfl_xor_sync(0xffffffffu, nsum, o);
                pmax  = fmaxf(pmax, __shfl_xor_sync(0xffffffffu, pmax, o));
                nmin  = fminf(nmin, __shfl_xor_sync(0xffffffffu, nmin, o));
            }
            if (lane < 4) {
                int lc = gj[ci] - j0;
                atomicAdd(&c_psum[lc], psum);
                atomicAdd(&c_nsum[lc], nsum);
                atomicMax(&c_pmax[lc], __float_as_uint(pmax));
                atomicMin(&c_nmin[lc], __float_as_uint(nmin));
            }
        }
    }

    __syncthreads();
    if (tid < BM) {
        int i = i0 + tid;
        atomicAdd(&g_pos_sum[i], r_psum[tid]);
        atomicAdd(&g_neg_sum[i], r_nsum[tid]);
        atomicMax(&g_pos_max[i], r_pmax[tid]);
        atomicMin(&g_neg_min[i], r_nmin[tid]);
        if (offdiag) {
            int j = j0 + tid;
            atomicAdd(&g_pos_sum[j], c_psum[tid]);
            atomicAdd(&g_neg_sum[j], c_nsum[tid]);
            atomicMax(&g_pos_max[j], c_pmax[tid]);
            atomicMin(&g_neg_min[j], c_nmin[tid]);
        }
    }
}

// ---------------------------------------------------------------------------
// Kernel 4: per-row loss terms + mean. 32 blocks; one atomicAdd per block.
// ---------------------------------------------------------------------------
__global__ void finalize_kernel(float* __restrict__ out)
{
    __shared__ float red[256];
    const int tid = threadIdx.x;
    const int r   = blockIdx.x * 256 + tid;

    int   h       = g_hist[g_cls[r]];
    float cnt_p   = (float)(h - 1);
    float cnt_n   = (float)(N - h);
    float sigma_p = g_pos_sum[r] / cnt_p;
    float sigma_n = g_neg_sum[r] / cnt_n;
    float ap = __uint_as_float(g_pos_max[r]) / sigma_p + 0.5f * logf(sigma_p);
    float an = __uint_as_float(g_neg_min[r]) / sigma_n + 0.5f * logf(sigma_n);
    float lsum = fmaxf(ap - an + MARGIN, 0.f);

    red[tid] = lsum;
    __syncthreads();
    #pragma unroll
    for (int s = 128; s > 0; s >>= 1) {
        if (tid < s) red[tid] += red[tid + s];
        __syncthreads();
    }
    if (tid == 0) atomicAdd(out, red[0] * (1.f / (float)N));
}

// ---------------------------------------------------------------------------
extern "C" void kernel_launch(void* const* d_in, const int* in_sizes, int n_in,
                              void* d_out, int out_size)
{
    const float* x = (const float*)d_in[0];
    const void*  t = d_in[1];
    int tgt_elems = (n_in > 1) ? in_sizes[1] : N;

    cudaFuncSetAttribute(dist_kernel, cudaFuncAttributeMaxDynamicSharedMemorySize,
                         SMEM_TOTAL);

    prep_kernel<<<N / 8, 256>>>(x);
    init2_kernel<<<(N + 255) / 256, 256>>>(t, tgt_elems, (float*)d_out);
    hist_kernel<<<(N + 255) / 256, 256>>>();
    dist_kernel<<<dim3(64, 64), 256, SMEM_TOTAL>>>();
    finalize_kernel<<<N / 256, 256>>>((float*)d_out);
}

// round 8
// speedup vs baseline: 2.7899x; 1.0003x over previous
#include <cuda_runtime.h>
#include <cuda_bf16.h>
#include <cstdint>

#define N 8192
#define D 128
#define NUM_CLASSES 256
#define MARGIN 0.3f

#define BM 128
#define BN 128
#define BKP 40                        // padded row: 80B = 20 banks, ldmatrix conflict-free
#define CHUNK_ELEMS (128 * BKP)       // 5120 bf16 per (rowblock, kchunk)
#define CHUNK_BYTES (CHUNK_ELEMS * 2) // 10240 B
#define STAGE_BYTES (4 * CHUNK_BYTES) // Ahi,Alo,Bhi,Blo = 40960 B
#define SMEM_DATA   (2 * STAGE_BYTES) // double buffered = 81920 B
#define SMEM_TOTAL  (SMEM_DATA + 16)  // + 2 mbarriers

// Persistent device state (module globals; no allocation).
__device__ float    g_sq[N];
__device__ int      g_cls[N];
__device__ float    g_pos_sum[N];
__device__ float    g_neg_sum[N];
__device__ unsigned g_pos_max[N];     // float bits; dsq > 0 so uint order == float order
__device__ unsigned g_neg_min[N];
__device__ int      g_hist[NUM_CLASSES];
// tile-major, pre-padded: [block 0..63][kchunk 0..3][row 0..127 * BKP + col]
__device__ __align__(16) __nv_bfloat16 g_xhi[N * 4 * BKP];
__device__ __align__(16) __nv_bfloat16 g_xlo[N * 4 * BKP];

__device__ __forceinline__ unsigned su32(const void* p) {
    return (unsigned)__cvta_generic_to_shared(p);
}

#define LDMX4(r0, r1, r2, r3, addr)                                         \
    asm volatile("ldmatrix.sync.aligned.m8n8.x4.shared.b16 {%0,%1,%2,%3}, [%4];" \
                 : "=r"(r0), "=r"(r1), "=r"(r2), "=r"(r3) : "r"(addr))

#define MMA_BF16(c0, c1, c2, c3, a, b)                                      \
    asm volatile("mma.sync.aligned.m16n8k16.row.col.f32.bf16.bf16.f32 "     \
                 "{%0,%1,%2,%3}, {%4,%5,%6,%7}, {%8,%9}, {%0,%1,%2,%3};"    \
                 : "+f"(c0), "+f"(c1), "+f"(c2), "+f"(c3)                    \
                 : "r"((a)[0]), "r"((a)[1]), "r"((a)[2]), "r"((a)[3]),       \
                   "r"((b)[0]), "r"((b)[1]))

__device__ __forceinline__ void mbar_wait(unsigned mbar, unsigned parity) {
    asm volatile("{\n\t.reg .pred P;\n\t"
                 "WL%=:\n\t"
                 "mbarrier.try_wait.parity.acquire.cta.shared::cta.b64 P, [%0], %1, 0x989680;\n\t"
                 "@P bra WD%=;\n\t"
                 "bra WL%=;\n\t"
                 "WD%=:\n\t}"
                 :: "r"(mbar), "r"(parity) : "memory");
}

// ---------------------------------------------------------------------------
// Kernel 1: warp-per-row. Squared norms + bf16 hi/lo split written in the
// padded tile-major layout so dist_kernel can bulk-copy chunks verbatim.
// ---------------------------------------------------------------------------
__global__ void prep_kernel(const float* __restrict__ x)
{
    int gt   = blockIdx.x * blockDim.x + threadIdx.x;
    int row  = gt >> 5;
    int lane = gt & 31;
    if (row >= N) return;

    float4 v = ((const float4*)(x + (size_t)row * D))[lane];
    float s = v.x * v.x + v.y * v.y + v.z * v.z + v.w * v.w;
    #pragma unroll
    for (int o = 16; o; o >>= 1) s += __shfl_xor_sync(0xffffffffu, s, o);
    if (lane == 0) g_sq[row] = s;

    float f[4] = {v.x, v.y, v.z, v.w};
    unsigned short h[4], l[4];
    #pragma unroll
    for (int k = 0; k < 4; k++) {
        __nv_bfloat16 bh = __float2bfloat16(f[k]);
        __nv_bfloat16 bl = __float2bfloat16(f[k] - __bfloat162float(bh));
        h[k] = __bfloat16_as_ushort(bh);
        l[k] = __bfloat16_as_ushort(bl);
    }
    uint2 uh, ul;
    uh.x = (unsigned)h[0] | ((unsigned)h[1] << 16);
    uh.y = (unsigned)h[2] | ((unsigned)h[3] << 16);
    ul.x = (unsigned)l[0] | ((unsigned)l[1] << 16);
    ul.y = (unsigned)l[2] | ((unsigned)l[3] << 16);

    // lane covers global cols 4*lane .. 4*lane+3  ->  kchunk = lane>>3, c = (lane&7)*4
    int blk = row >> 7, r = row & 127;
    size_t off = (size_t)(blk * 4 + (lane >> 3)) * CHUNK_ELEMS + r * BKP + (lane & 7) * 4;
    *(uint2*)(g_xhi + off) = uh;
    *(uint2*)(g_xlo + off) = ul;
}

// ---------------------------------------------------------------------------
// Kernel 2: targets (dtype auto-detect) + accumulator/hist/out reset.
// ---------------------------------------------------------------------------
__global__ void init2_kernel(const void* __restrict__ tgt, int tgt_elems,
                             float* __restrict__ out)
{
    __shared__ int s_is64;
    if (threadIdx.x == 0) {
        const long long* t64 = (const long long*)tgt;
        int is64 = 1;
        int probe = tgt_elems < 8 ? tgt_elems : 8;
        for (int i = 0; i < probe; i++) {
            long long v = t64[i];
            if (v < 0 || v >= NUM_CLASSES) { is64 = 0; break; }
        }
        s_is64 = is64;
    }
    __syncthreads();
    int r = blockIdx.x * blockDim.x + threadIdx.x;
    if (r < N) {
        int c;
        if (s_is64) c = (int)((const long long*)tgt)[r];
        else        c = ((const int*)tgt)[r];
        g_cls[r]     = c;
        g_pos_sum[r] = 0.f;
        g_neg_sum[r] = 0.f;
        g_pos_max[r] = 0u;
        g_neg_min[r] = 0x7F800000u;
    }
    if (r < NUM_CLASSES) g_hist[r] = 0;
    if (r == 0) out[0] = 0.f;
}

__global__ void hist_kernel()
{
    int r = blockIdx.x * blockDim.x + threadIdx.x;
    if (r < N) atomicAdd(&g_hist[g_cls[r]], 1);
}

// ---------------------------------------------------------------------------
// Kernel 3: triangular tiled X*X^T, bf16-split mma.sync, cp.async.bulk
// double-buffered tile feed. Term-major MMA issue for ILP.
// ---------------------------------------------------------------------------
__device__ __forceinline__ void issue_stage(unsigned sbase, int s, int kb,
                                            int by, int bx)
{
    unsigned mbar = sbase + SMEM_DATA + s * 8;
    asm volatile("mbarrier.arrive.expect_tx.shared.b64 _, [%0], %1;"
                 :: "r"(mbar), "r"((unsigned)STAGE_BYTES) : "memory");
    const __nv_bfloat16* srcs[4] = {
        g_xhi + (size_t)(by * 4 + kb) * CHUNK_ELEMS,
        g_xlo + (size_t)(by * 4 + kb) * CHUNK_ELEMS,
        g_xhi + (size_t)(bx * 4 + kb) * CHUNK_ELEMS,
        g_xlo + (size_t)(bx * 4 + kb) * CHUNK_ELEMS
    };
    #pragma unroll
    for (int o = 0; o < 4; o++) {
        unsigned dst = sbase + (unsigned)(s * 4 + o) * CHUNK_BYTES;
        asm volatile("cp.async.bulk.shared::cluster.global.mbarrier::complete_tx::bytes "
                     "[%0], [%1], %2, [%3];"
                     :: "r"(dst), "l"(srcs[o]), "r"((unsigned)CHUNK_BYTES), "r"(mbar)
                     : "memory");
    }
}

__global__ __launch_bounds__(256) void dist_kernel()
{
    const int bx = blockIdx.x, by = blockIdx.y;
    if (bx < by) return;
    const bool offdiag = (bx != by);
    const int i0 = by * BM, j0 = bx * BN;

    extern __shared__ char smem[];
    const unsigned sbase = su32(smem);

    __shared__ float    r_psum[BM], r_nsum[BM];
    __shared__ unsigned r_pmax[BM], r_nmin[BM];
    __shared__ float    c_psum[BN], c_nsum[BN];
    __shared__ unsigned c_pmax[BN], c_nmin[BN];

    const int tid = threadIdx.x;
    const int wid = tid >> 5, lane = tid & 31;
    const int warp_m = (wid >> 2) * 64;   // 0 or 64
    const int warp_n = (wid & 3) * 32;    // 0,32,64,96

    if (tid < BM) {
        r_psum[tid] = 0.f; r_nsum[tid] = 0.f; r_pmax[tid] = 0u; r_nmin[tid] = 0x7F800000u;
        c_psum[tid] = 0.f; c_nsum[tid] = 0.f; c_pmax[tid] = 0u; c_nmin[tid] = 0x7F800000u;
    }
    if (tid == 0) {
        asm volatile("mbarrier.init.shared.b64 [%0], %1;"
                     :: "r"(sbase + SMEM_DATA), "r"(1u) : "memory");
        asm volatile("mbarrier.init.shared.b64 [%0], %1;"
                     :: "r"(sbase + SMEM_DATA + 8), "r"(1u) : "memory");
    }
    __syncthreads();
    if (tid == 0) {
        issue_stage(sbase, 0, 0, by, bx);
        issue_stage(sbase, 1, 1, by, bx);
    }

    float C[8][8];
    #pragma unroll
    for (int a = 0; a < 8; a++)
        #pragma unroll
        for (int b = 0; b < 8; b++) C[a][b] = 0.f;

    // per-lane ldmatrix byte offsets within a 16x16 tile (80B row pitch)
    const unsigned aoff = (unsigned)(lane & 15) * (BKP * 2) + (unsigned)(lane >> 4) * 16
                        + (unsigned)warp_m * (BKP * 2);
    const unsigned boff = (unsigned)(((lane >> 4) & 1) * 8 + (lane & 7)) * (BKP * 2)
                        + (unsigned)((lane >> 3) & 1) * 16
                        + (unsigned)warp_n * (BKP * 2);

    for (int kb = 0; kb < 4; kb++) {
        const int s = kb & 1;
        mbar_wait(sbase + SMEM_DATA + s * 8, (unsigned)(kb >> 1));

        const unsigned sb = sbase + (unsigned)s * STAGE_BYTES;
        // hoisted base addresses for this stage
        const unsigned aAhi = sb + aoff;
        const unsigned aAlo = sb + CHUNK_BYTES + aoff;
        const unsigned aBhi = sb + 2 * CHUNK_BYTES + boff;
        const unsigned aBlo = sb + 3 * CHUNK_BYTES + boff;

        #pragma unroll
        for (int ks = 0; ks < 2; ks++) {
            const unsigned kbyte = (unsigned)ks * 32;  // 16 bf16 = 32B
            unsigned Ahi[4][4], Alo[4][4], Bhi[4][2], Blo[4][2];
            #pragma unroll
            for (int mt = 0; mt < 4; mt++) {
                const unsigned moff = (unsigned)(mt * 16) * (BKP * 2) + kbyte;
                LDMX4(Ahi[mt][0], Ahi[mt][1], Ahi[mt][2], Ahi[mt][3], aAhi + moff);
                LDMX4(Alo[mt][0], Alo[mt][1], Alo[mt][2], Alo[mt][3], aAlo + moff);
            }
            #pragma unroll
            for (int bq = 0; bq < 2; bq++) {
                const unsigned noff = (unsigned)(bq * 16) * (BKP * 2) + kbyte;
                unsigned r0, r1, r2, r3;
                LDMX4(r0, r1, r2, r3, aBhi + noff);
                Bhi[2 * bq][0] = r0; Bhi[2 * bq][1] = r1;
                Bhi[2 * bq + 1][0] = r2; Bhi[2 * bq + 1][1] = r3;
                LDMX4(r0, r1, r2, r3, aBlo + noff);
                Blo[2 * bq][0] = r0; Blo[2 * bq][1] = r1;
                Blo[2 * bq + 1][0] = r2; Blo[2 * bq + 1][1] = r3;
            }
            // term-major issue: 16 independent MMAs between accumulator reuses
            #pragma unroll
            for (int mt = 0; mt < 4; mt++)
                #pragma unroll
                for (int nt = 0; nt < 4; nt++)
                    MMA_BF16(C[2*mt][2*nt], C[2*mt][2*nt+1], C[2*mt+1][2*nt], C[2*mt+1][2*nt+1],
                             Ahi[mt], Bhi[nt]);
            #pragma unroll
            for (int mt = 0; mt < 4; mt++)
                #pragma unroll
                for (int nt = 0; nt < 4; nt++)
                    MMA_BF16(C[2*mt][2*nt], C[2*mt][2*nt+1], C[2*mt+1][2*nt], C[2*mt+1][2*nt+1],
                             Ahi[mt], Blo[nt]);
            #pragma unroll
            for (int mt = 0; mt < 4; mt++)
                #pragma unroll
                for (int nt = 0; nt < 4; nt++)
                    MMA_BF16(C[2*mt][2*nt], C[2*mt][2*nt+1], C[2*mt+1][2*nt], C[2*mt+1][2*nt+1],
                             Alo[mt], Bhi[nt]);
        }
        __syncthreads();                 // all warps done reading stage s
        if (tid == 0 && kb < 2) issue_stage(sbase, s, kb + 2, by, bx);
    }

    // ---- epilogue ----
    const int rg = lane >> 2, cg = lane & 3;
    int   gi[8], gj[8], clsi[8], clsj[8];
    float sqi[8], sqj[8];
    #pragma unroll
    for (int mi = 0; mi < 8; mi++) {
        int lr = warp_m + (mi >> 1) * 16 + (mi & 1) * 8 + rg;
        gi[mi]   = i0 + lr;
        sqi[mi]  = g_sq[gi[mi]];
        clsi[mi] = g_cls[gi[mi]];
    }
    #pragma unroll
    for (int ci = 0; ci < 8; ci++) {
        int lc = warp_n + (ci >> 1) * 8 + 2 * cg + (ci & 1);
        gj[ci]   = j0 + lc;
        sqj[ci]  = g_sq[gj[ci]];
        clsj[ci] = g_cls[gj[ci]];
    }
    #pragma unroll
    for (int mi = 0; mi < 8; mi++)
        #pragma unroll
        for (int ci = 0; ci < 8; ci++)
            C[mi][ci] = fmaxf(sqi[mi] + sqj[ci] - 2.f * C[mi][ci], 1e-12f);

    // row pass: reductions over the 8 columns per thread, then quad shuffle
    #pragma unroll
    for (int mi = 0; mi < 8; mi++) {
        float psum = 0.f, nsum = 0.f;
        float pmax = 0.f, nmin = __uint_as_float(0x7F800000u);
        #pragma unroll
        for (int ci = 0; ci < 8; ci++) {
            float dsq = C[mi][ci];
            if (clsi[mi] == clsj[ci]) {
                if (gi[mi] != gj[ci]) {   // reference drops the self element
                    psum += dsq;
                    pmax  = fmaxf(pmax, dsq);
                }
            } else {
                nsum += dsq;
                nmin  = fminf(nmin, dsq);
            }
        }
        #pragma unroll
        for (int o = 1; o <= 2; o <<= 1) {
            psum += __shfl_xor_sync(0xffffffffu, psum, o);
            nsum += __shfl_xor_sync(0xffffffffu, nsum, o);
            pmax  = fmaxf(pmax, __shfl_xor_sync(0xffffffffu, pmax, o));
            nmin  = fminf(nmin, __shfl_xor_sync(0xffffffffu, nmin, o));
        }
        if (cg == 0) {
            int lr = gi[mi] - i0;
            atomicAdd(&r_psum[lr], psum);
            atomicAdd(&r_nsum[lr], nsum);
            atomicMax(&r_pmax[lr], __float_as_uint(pmax));
            atomicMin(&r_nmin[lr], __float_as_uint(nmin));
        }
    }

    // column pass (symmetry: row-j reductions) for off-diagonal tiles
    if (offdiag) {
        #pragma unroll
        for (int ci = 0; ci < 8; ci++) {
            float psum = 0.f, nsum = 0.f;
            float pmax = 0.f, nmin = __uint_as_float(0x7F800000u);
            #pragma unroll
            for (int mi = 0; mi < 8; mi++) {
                float dsq = C[mi][ci];
                if (clsi[mi] == clsj[ci]) {
                    psum += dsq;
                    pmax  = fmaxf(pmax, dsq);
                } else {
                    nsum += dsq;
                    nmin  = fminf(nmin, dsq);
                }
            }
            #pragma unroll
            for (int o = 4; o <= 16; o <<= 1) {
                psum += __shfl_xor_sync(0xffffffffu, psum, o);
                nsum += __shfl_xor_sync(0xffffffffu, nsum, o);
                pmax  = fmaxf(pmax, __shfl_xor_sync(0xffffffffu, pmax, o));
                nmin  = fminf(nmin, __shfl_xor_sync(0xffffffffu, nmin, o));
            }
            if (lane < 4) {
                int lc = gj[ci] - j0;
                atomicAdd(&c_psum[lc], psum);
                atomicAdd(&c_nsum[lc], nsum);
                atomicMax(&c_pmax[lc], __float_as_uint(pmax));
                atomicMin(&c_nmin[lc], __float_as_uint(nmin));
            }
        }
    }

    __syncthreads();
    if (tid < BM) {
        int i = i0 + tid;
        atomicAdd(&g_pos_sum[i], r_psum[tid]);
        atomicAdd(&g_neg_sum[i], r_nsum[tid]);
        atomicMax(&g_pos_max[i], r_pmax[tid]);
        atomicMin(&g_neg_min[i], r_nmin[tid]);
        if (offdiag) {
            int j = j0 + tid;
            atomicAdd(&g_pos_sum[j], c_psum[tid]);
            atomicAdd(&g_neg_sum[j], c_nsum[tid]);
            atomicMax(&g_pos_max[j], c_pmax[tid]);
            atomicMin(&g_neg_min[j], c_nmin[tid]);
        }
    }
}

// ---------------------------------------------------------------------------
// Kernel 4: per-row loss terms + mean. 32 blocks; one atomicAdd per block.
// ---------------------------------------------------------------------------
__global__ void finalize_kernel(float* __restrict__ out)
{
    __shared__ float red[256];
    const int tid = threadIdx.x;
    const int r   = blockIdx.x * 256 + tid;

    int   h       = g_hist[g_cls[r]];
    float cnt_p   = (float)(h - 1);
    float cnt_n   = (float)(N - h);
    float sigma_p = g_pos_sum[r] / cnt_p;
    float sigma_n = g_neg_sum[r] / cnt_n;
    float ap = __uint_as_float(g_pos_max[r]) / sigma_p + 0.5f * logf(sigma_p);
    float an = __uint_as_float(g_neg_min[r]) / sigma_n + 0.5f * logf(sigma_n);
    float lsum = fmaxf(ap - an + MARGIN, 0.f);

    red[tid] = lsum;
    __syncthreads();
    #pragma unroll
    for (int s = 128; s > 0; s >>= 1) {
        if (tid < s) red[tid] += red[tid + s];
        __syncthreads();
    }
    if (tid == 0) atomicAdd(out, red[0] * (1.f / (float)N));
}

// ---------------------------------------------------------------------------
extern "C" void kernel_launch(void* const* d_in, const int* in_sizes, int n_in,
                              void* d_out, int out_size)
{
    const float* x = (const float*)d_in[0];
    const void*  t = d_in[1];
    int tgt_elems = (n_in > 1) ? in_sizes[1] : N;

    cudaFuncSetAttribute(dist_kernel, cudaFuncAttributeMaxDynamicSharedMemorySize,
                         SMEM_TOTAL);

    prep_kernel<<<N / 8, 256>>>(x);
    init2_kernel<<<(N + 255) / 256, 256>>>(t, tgt_elems, (float*)d_out);
    hist_kernel<<<(N + 255) / 256, 256>>>();
    dist_kernel<<<dim3(64, 64), 256, SMEM_TOTAL>>>();
    finalize_kernel<<<N / 256, 256>>>((float*)d_out);
}

// round 9
// speedup vs baseline: 3.8133x; 1.3668x over previous
#include <cuda_runtime.h>
#include <cuda_fp16.h>
#include <cstdint>

#define N 8192
#define D 128
#define NUM_CLASSES 256
#define MARGIN 0.3f

#define BM 128
#define BN 128
#define BKP 40                        // padded row: 80B = 20 banks, ldmatrix conflict-free
#define CHUNK_ELEMS (128 * BKP)       // 5120 fp16 per (rowblock, kchunk)
#define CHUNK_BYTES (CHUNK_ELEMS * 2) // 10240 B
#define STAGE_BYTES (2 * CHUNK_BYTES) // A, B = 20480 B
#define SMEM_DATA   (2 * STAGE_BYTES) // double buffered = 40960 B
#define SMEM_TOTAL  (SMEM_DATA + 16)  // + 2 mbarriers

// Persistent device state (module globals; no allocation).
__device__ float    g_sq[N];
__device__ int      g_cls[N];
__device__ float    g_pos_sum[N];
__device__ float    g_neg_sum[N];
__device__ unsigned g_pos_max[N];     // float bits; dsq > 0 so uint order == float order
__device__ unsigned g_neg_min[N];
__device__ int      g_hist[NUM_CLASSES];
// tile-major, pre-padded: [block 0..63][kchunk 0..3][row 0..127 * BKP + col]
__device__ __align__(16) __half g_xh[N * 4 * BKP];

__device__ __forceinline__ unsigned su32(const void* p) {
    return (unsigned)__cvta_generic_to_shared(p);
}

#define LDMX4(r0, r1, r2, r3, addr)                                         \
    asm volatile("ldmatrix.sync.aligned.m8n8.x4.shared.b16 {%0,%1,%2,%3}, [%4];" \
                 : "=r"(r0), "=r"(r1), "=r"(r2), "=r"(r3) : "r"(addr))

#define MMA_F16(c0, c1, c2, c3, a, b)                                       \
    asm volatile("mma.sync.aligned.m16n8k16.row.col.f32.f16.f16.f32 "       \
                 "{%0,%1,%2,%3}, {%4,%5,%6,%7}, {%8,%9}, {%0,%1,%2,%3};"    \
                 : "+f"(c0), "+f"(c1), "+f"(c2), "+f"(c3)                    \
                 : "r"((a)[0]), "r"((a)[1]), "r"((a)[2]), "r"((a)[3]),       \
                   "r"((b)[0]), "r"((b)[1]))

__device__ __forceinline__ void mbar_wait(unsigned mbar, unsigned parity) {
    asm volatile("{\n\t.reg .pred P;\n\t"
                 "WL%=:\n\t"
                 "mbarrier.try_wait.parity.acquire.cta.shared::cta.b64 P, [%0], %1, 0x989680;\n\t"
                 "@P bra WD%=;\n\t"
                 "bra WL%=;\n\t"
                 "WD%=:\n\t}"
                 :: "r"(mbar), "r"(parity) : "memory");
}

// ---------------------------------------------------------------------------
// Kernel 1: warp-per-row. Squared norms (fp32) + fp16 cast of X written in the
// padded tile-major layout so dist_kernel can bulk-copy chunks verbatim.
// ---------------------------------------------------------------------------
__global__ void prep_kernel(const float* __restrict__ x)
{
    int gt   = blockIdx.x * blockDim.x + threadIdx.x;
    int row  = gt >> 5;
    int lane = gt & 31;
    if (row >= N) return;

    float4 v = ((const float4*)(x + (size_t)row * D))[lane];
    float s = v.x * v.x + v.y * v.y + v.z * v.z + v.w * v.w;
    #pragma unroll
    for (int o = 16; o; o >>= 1) s += __shfl_xor_sync(0xffffffffu, s, o);
    if (lane == 0) g_sq[row] = s;

    float f[4] = {v.x, v.y, v.z, v.w};
    unsigned short h[4];
    #pragma unroll
    for (int k = 0; k < 4; k++)
        h[k] = __half_as_ushort(__float2half_rn(f[k]));
    uint2 uh;
    uh.x = (unsigned)h[0] | ((unsigned)h[1] << 16);
    uh.y = (unsigned)h[2] | ((unsigned)h[3] << 16);

    // lane covers global cols 4*lane .. 4*lane+3  ->  kchunk = lane>>3, c = (lane&7)*4
    int blk = row >> 7, r = row & 127;
    size_t off = (size_t)(blk * 4 + (lane >> 3)) * CHUNK_ELEMS + r * BKP + (lane & 7) * 4;
    *(uint2*)(g_xh + off) = uh;
}

// ---------------------------------------------------------------------------
// Kernel 2: targets (dtype auto-detect) + accumulator/hist/out reset.
// ---------------------------------------------------------------------------
__global__ void init2_kernel(const void* __restrict__ tgt, int tgt_elems,
                             float* __restrict__ out)
{
    __shared__ int s_is64;
    if (threadIdx.x == 0) {
        const long long* t64 = (const long long*)tgt;
        int is64 = 1;
        int probe = tgt_elems < 8 ? tgt_elems : 8;
        for (int i = 0; i < probe; i++) {
            long long v = t64[i];
            if (v < 0 || v >= NUM_CLASSES) { is64 = 0; break; }
        }
        s_is64 = is64;
    }
    __syncthreads();
    int r = blockIdx.x * blockDim.x + threadIdx.x;
    if (r < N) {
        int c;
        if (s_is64) c = (int)((const long long*)tgt)[r];
        else        c = ((const int*)tgt)[r];
        g_cls[r]     = c;
        g_pos_sum[r] = 0.f;
        g_neg_sum[r] = 0.f;
        g_pos_max[r] = 0u;
        g_neg_min[r] = 0x7F800000u;
    }
    if (r < NUM_CLASSES) g_hist[r] = 0;
    if (r == 0) out[0] = 0.f;
}

__global__ void hist_kernel()
{
    int r = blockIdx.x * blockDim.x + threadIdx.x;
    if (r < N) atomicAdd(&g_hist[g_cls[r]], 1);
}

// ---------------------------------------------------------------------------
// Kernel 3: triangular tiled X*X^T, single-term fp16 mma.sync, cp.async.bulk
// double-buffered tile feed.
// ---------------------------------------------------------------------------
__device__ __forceinline__ void issue_stage(unsigned sbase, int s, int kb,
                                            int by, int bx)
{
    unsigned mbar = sbase + SMEM_DATA + s * 8;
    asm volatile("mbarrier.arrive.expect_tx.shared.b64 _, [%0], %1;"
                 :: "r"(mbar), "r"((unsigned)STAGE_BYTES) : "memory");
    const __half* srcs[2] = {
        g_xh + (size_t)(by * 4 + kb) * CHUNK_ELEMS,
        g_xh + (size_t)(bx * 4 + kb) * CHUNK_ELEMS
    };
    #pragma unroll
    for (int o = 0; o < 2; o++) {
        unsigned dst = sbase + (unsigned)(s * 2 + o) * CHUNK_BYTES;
        asm volatile("cp.async.bulk.shared::cluster.global.mbarrier::complete_tx::bytes "
                     "[%0], [%1], %2, [%3];"
                     :: "r"(dst), "l"(srcs[o]), "r"((unsigned)CHUNK_BYTES), "r"(mbar)
                     : "memory");
    }
}

__global__ __launch_bounds__(256) void dist_kernel()
{
    const int bx = blockIdx.x, by = blockIdx.y;
    if (bx < by) return;
    const bool offdiag = (bx != by);
    const int i0 = by * BM, j0 = bx * BN;

    extern __shared__ char smem[];
    const unsigned sbase = su32(smem);

    __shared__ float    r_psum[BM], r_nsum[BM];
    __shared__ unsigned r_pmax[BM], r_nmin[BM];
    __shared__ float    c_psum[BN], c_nsum[BN];
    __shared__ unsigned c_pmax[BN], c_nmin[BN];

    const int tid = threadIdx.x;
    const int wid = tid >> 5, lane = tid & 31;
    const int warp_m = (wid >> 2) * 64;   // 0 or 64
    const int warp_n = (wid & 3) * 32;    // 0,32,64,96

    if (tid < BM) {
        r_psum[tid] = 0.f; r_nsum[tid] = 0.f; r_pmax[tid] = 0u; r_nmin[tid] = 0x7F800000u;
        c_psum[tid] = 0.f; c_nsum[tid] = 0.f; c_pmax[tid] = 0u; c_nmin[tid] = 0x7F800000u;
    }
    if (tid == 0) {
        asm volatile("mbarrier.init.shared.b64 [%0], %1;"
                     :: "r"(sbase + SMEM_DATA), "r"(1u) : "memory");
        asm volatile("mbarrier.init.shared.b64 [%0], %1;"
                     :: "r"(sbase + SMEM_DATA + 8), "r"(1u) : "memory");
    }
    __syncthreads();
    if (tid == 0) {
        issue_stage(sbase, 0, 0, by, bx);
        issue_stage(sbase, 1, 1, by, bx);
    }

    float C[8][8];
    #pragma unroll
    for (int a = 0; a < 8; a++)
        #pragma unroll
        for (int b = 0; b < 8; b++) C[a][b] = 0.f;

    // per-lane ldmatrix byte offsets within a 16x16 tile (80B row pitch)
    const unsigned aoff = (unsigned)(lane & 15) * (BKP * 2) + (unsigned)(lane >> 4) * 16
                        + (unsigned)warp_m * (BKP * 2);
    const unsigned boff = (unsigned)(((lane >> 4) & 1) * 8 + (lane & 7)) * (BKP * 2)
                        + (unsigned)((lane >> 3) & 1) * 16
                        + (unsigned)warp_n * (BKP * 2);

    for (int kb = 0; kb < 4; kb++) {
        const int s = kb & 1;
        mbar_wait(sbase + SMEM_DATA + s * 8, (unsigned)(kb >> 1));

        const unsigned sb = sbase + (unsigned)s * STAGE_BYTES;
        const unsigned aA = sb + aoff;
        const unsigned aB = sb + CHUNK_BYTES + boff;

        #pragma unroll
        for (int ks = 0; ks < 2; ks++) {
            const unsigned kbyte = (unsigned)ks * 32;  // 16 fp16 = 32B
            unsigned A[4][4], B[4][2];
            #pragma unroll
            for (int mt = 0; mt < 4; mt++) {
                const unsigned moff = (unsigned)(mt * 16) * (BKP * 2) + kbyte;
                LDMX4(A[mt][0], A[mt][1], A[mt][2], A[mt][3], aA + moff);
            }
            #pragma unroll
            for (int bq = 0; bq < 2; bq++) {
                const unsigned noff = (unsigned)(bq * 16) * (BKP * 2) + kbyte;
                unsigned r0, r1, r2, r3;
                LDMX4(r0, r1, r2, r3, aB + noff);
                B[2 * bq][0] = r0; B[2 * bq][1] = r1;
                B[2 * bq + 1][0] = r2; B[2 * bq + 1][1] = r3;
            }
            #pragma unroll
            for (int mt = 0; mt < 4; mt++)
                #pragma unroll
                for (int nt = 0; nt < 4; nt++)
                    MMA_F16(C[2*mt][2*nt], C[2*mt][2*nt+1], C[2*mt+1][2*nt], C[2*mt+1][2*nt+1],
                            A[mt], B[nt]);
        }
        __syncthreads();                 // all warps done reading stage s
        if (tid == 0 && kb < 2) issue_stage(sbase, s, kb + 2, by, bx);
    }

    // ---- epilogue ----
    const int rg = lane >> 2, cg = lane & 3;
    int   gi[8], gj[8], clsi[8], clsj[8];
    float sqi[8], sqj[8];
    #pragma unroll
    for (int mi = 0; mi < 8; mi++) {
        int lr = warp_m + (mi >> 1) * 16 + (mi & 1) * 8 + rg;
        gi[mi]   = i0 + lr;
        sqi[mi]  = g_sq[gi[mi]];
        clsi[mi] = g_cls[gi[mi]];
    }
    #pragma unroll
    for (int ci = 0; ci < 8; ci++) {
        int lc = warp_n + (ci >> 1) * 8 + 2 * cg + (ci & 1);
        gj[ci]   = j0 + lc;
        sqj[ci]  = g_sq[gj[ci]];
        clsj[ci] = g_cls[gj[ci]];
    }
    #pragma unroll
    for (int mi = 0; mi < 8; mi++)
        #pragma unroll
        for (int ci = 0; ci < 8; ci++)
            C[mi][ci] = fmaxf(sqi[mi] + sqj[ci] - 2.f * C[mi][ci], 1e-12f);

    // row pass: reductions over the 8 columns per thread, then quad shuffle
    #pragma unroll
    for (int mi = 0; mi < 8; mi++) {
        float psum = 0.f, nsum = 0.f;
        float pmax = 0.f, nmin = __uint_as_float(0x7F800000u);
        #pragma unroll
        for (int ci = 0; ci < 8; ci++) {
            float dsq = C[mi][ci];
            if (clsi[mi] == clsj[ci]) {
                if (gi[mi] != gj[ci]) {   // reference drops the self element
                    psum += dsq;
                    pmax  = fmaxf(pmax, dsq);
                }
            } else {
                nsum += dsq;
                nmin  = fminf(nmin, dsq);
            }
        }
        #pragma unroll
        for (int o = 1; o <= 2; o <<= 1) {
            psum += __shfl_xor_sync(0xffffffffu, psum, o);
            nsum += __shfl_xor_sync(0xffffffffu, nsum, o);
            pmax  = fmaxf(pmax, __shfl_xor_sync(0xffffffffu, pmax, o));
            nmin  = fminf(nmin, __shfl_xor_sync(0xffffffffu, nmin, o));
        }
        if (cg == 0) {
            int lr = gi[mi] - i0;
            atomicAdd(&r_psum[lr], psum);
            atomicAdd(&r_nsum[lr], nsum);
            atomicMax(&r_pmax[lr], __float_as_uint(pmax));
            atomicMin(&r_nmin[lr], __float_as_uint(nmin));
        }
    }

    // column pass (symmetry: row-j reductions) for off-diagonal tiles
    if (offdiag) {
        #pragma unroll
        for (int ci = 0; ci < 8; ci++) {
            float psum = 0.f, nsum = 0.f;
            float pmax = 0.f, nmin = __uint_as_float(0x7F800000u);
            #pragma unroll
            for (int mi = 0; mi < 8; mi++) {
                float dsq = C[mi][ci];
                if (clsi[mi] == clsj[ci]) {
                    psum += dsq;
                    pmax  = fmaxf(pmax, dsq);
                } else {
                    nsum += dsq;
                    nmin  = fminf(nmin, dsq);
                }
            }
            #pragma unroll
            for (int o = 4; o <= 16; o <<= 1) {
                psum += __shfl_xor_sync(0xffffffffu, psum, o);
                nsum += __shfl_xor_sync(0xffffffffu, nsum, o);
                pmax  = fmaxf(pmax, __shfl_xor_sync(0xffffffffu, pmax, o));
                nmin  = fminf(nmin, __shfl_xor_sync(0xffffffffu, nmin, o));
            }
            if (lane < 4) {
                int lc = gj[ci] - j0;
                atomicAdd(&c_psum[lc], psum);
                atomicAdd(&c_nsum[lc], nsum);
                atomicMax(&c_pmax[lc], __float_as_uint(pmax));
                atomicMin(&c_nmin[lc], __float_as_uint(nmin));
            }
        }
    }

    __syncthreads();
    if (tid < BM) {
        int i = i0 + tid;
        atomicAdd(&g_pos_sum[i], r_psum[tid]);
        atomicAdd(&g_neg_sum[i], r_nsum[tid]);
        atomicMax(&g_pos_max[i], r_pmax[tid]);
        atomicMin(&g_neg_min[i], r_nmin[tid]);
        if (offdiag) {
            int j = j0 + tid;
            atomicAdd(&g_pos_sum[j], c_psum[tid]);
            atomicAdd(&g_neg_sum[j], c_nsum[tid]);
            atomicMax(&g_pos_max[j], c_pmax[tid]);
            atomicMin(&g_neg_min[j], c_nmin[tid]);
        }
    }
}

// ---------------------------------------------------------------------------
// Kernel 4: per-row loss terms + mean. 32 blocks; one atomicAdd per block.
// ---------------------------------------------------------------------------
__global__ void finalize_kernel(float* __restrict__ out)
{
    __shared__ float red[256];
    const int tid = threadIdx.x;
    const int r   = blockIdx.x * 256 + tid;

    int   h       = g_hist[g_cls[r]];
    float cnt_p   = (float)(h - 1);
    float cnt_n   = (float)(N - h);
    float sigma_p = g_pos_sum[r] / cnt_p;
    float sigma_n = g_neg_sum[r] / cnt_n;
    float ap = __uint_as_float(g_pos_max[r]) / sigma_p + 0.5f * logf(sigma_p);
    float an = __uint_as_float(g_neg_min[r]) / sigma_n + 0.5f * logf(sigma_n);
    float lsum = fmaxf(ap - an + MARGIN, 0.f);

    red[tid] = lsum;
    __syncthreads();
    #pragma unroll
    for (int s = 128; s > 0; s >>= 1) {
        if (tid < s) red[tid] += red[tid + s];
        __syncthreads();
    }
    if (tid == 0) atomicAdd(out, red[0] * (1.f / (float)N));
}

// ---------------------------------------------------------------------------
extern "C" void kernel_launch(void* const* d_in, const int* in_sizes, int n_in,
                              void* d_out, int out_size)
{
    const float* x = (const float*)d_in[0];
    const void*  t = d_in[1];
    int tgt_elems = (n_in > 1) ? in_sizes[1] : N;

    cudaFuncSetAttribute(dist_kernel, cudaFuncAttributeMaxDynamicSharedMemorySize,
                         SMEM_TOTAL);

    prep_kernel<<<N / 8, 256>>>(x);
    init2_kernel<<<(N + 255) / 256, 256>>>(t, tgt_elems, (float*)d_out);
    hist_kernel<<<(N + 255) / 256, 256>>>();
    dist_kernel<<<dim3(64, 64), 256, SMEM_TOTAL>>>();
    finalize_kernel<<<N / 256, 256>>>((float*)d_out);
}